// round 6
// baseline (speedup 1.0000x reference)
#include <cuda_runtime.h>
#include <cuda_bf16.h>

#define T_TOK 4096
#define DMODEL 1024
#define NEXP 8
#define FFN 2048
#define TOPK 2
#define NPAIR (T_TOK * TOPK)

// ---------------- device scratch ----------------
__device__ int   g_cnt[NEXP];
__device__ int   g_off[NEXP + 1];
__device__ int   g_fill[NEXP];
__device__ int   g_pair_tok[NPAIR];
__device__ float g_pair_gate[NPAIR];
__device__ int   g_top_e[NPAIR];
__device__ float g_top_w[NPAIR];

__device__ __align__(16) __nv_bfloat16 g_xs_hi[(size_t)T_TOK * DMODEL];
__device__ __align__(16) __nv_bfloat16 g_xs_lo[(size_t)T_TOK * DMODEL];
__device__ __align__(16) __nv_bfloat16 g_w1_hi[(size_t)NEXP * FFN * DMODEL];
__device__ __align__(16) __nv_bfloat16 g_w1_lo[(size_t)NEXP * FFN * DMODEL];
__device__ __align__(16) __nv_bfloat16 g_v1_hi[(size_t)NEXP * FFN * DMODEL];
__device__ __align__(16) __nv_bfloat16 g_v1_lo[(size_t)NEXP * FFN * DMODEL];
__device__ __align__(16) __nv_bfloat16 g_w2t_hi[(size_t)NEXP * DMODEL * FFN];
__device__ __align__(16) __nv_bfloat16 g_w2t_lo[(size_t)NEXP * DMODEL * FFN];
__device__ __align__(16) __nv_bfloat16 g_h_hi[(size_t)NPAIR * FFN];
__device__ __align__(16) __nv_bfloat16 g_h_lo[(size_t)NPAIR * FFN];

// ---------------- helpers ----------------
__device__ __forceinline__ unsigned smem_u32(const void* p) {
    unsigned a;
    asm("{ .reg .u64 t; cvta.to.shared.u64 t, %1; cvt.u32.u64 %0, t; }"
        : "=r"(a) : "l"(p));
    return a;
}
// swizzled byte offset in a [rows][32 bf16] tile (64B rows); c must be < 64
__device__ __forceinline__ unsigned swz(int row, int c) {
    return (unsigned)(row * 64 + (c ^ ((row & 6) << 3)));
}
__device__ __forceinline__ void ldm4(unsigned* r, unsigned addr) {
    asm volatile("ldmatrix.sync.aligned.m8n8.x4.shared.b16 {%0,%1,%2,%3}, [%4];"
                 : "=r"(r[0]), "=r"(r[1]), "=r"(r[2]), "=r"(r[3]) : "r"(addr));
}
__device__ __forceinline__ void mma16816(float* c, const unsigned* a, const unsigned* b) {
    asm volatile(
        "mma.sync.aligned.m16n8k16.row.col.f32.bf16.bf16.f32 "
        "{%0,%1,%2,%3}, {%4,%5,%6,%7}, {%8,%9}, {%0,%1,%2,%3};"
        : "+f"(c[0]), "+f"(c[1]), "+f"(c[2]), "+f"(c[3])
        : "r"(a[0]), "r"(a[1]), "r"(a[2]), "r"(a[3]), "r"(b[0]), "r"(b[1]));
}
// pack (a->lo, b->hi) bf16x2, return residuals
__device__ __forceinline__ unsigned bf2_hi(float a, float b, float& ra, float& rb) {
    unsigned h;
    asm("cvt.rn.bf16x2.f32 %0, %1, %2;" : "=r"(h) : "f"(b), "f"(a));
    ra = a - __uint_as_float(h << 16);
    rb = b - __uint_as_float(h & 0xffff0000u);
    return h;
}
__device__ __forceinline__ unsigned bf2(float a, float b) {
    unsigned h;
    asm("cvt.rn.bf16x2.f32 %0, %1, %2;" : "=r"(h) : "f"(b), "f"(a));
    return h;
}

// ---------------- init ----------------
__global__ void init_kernel(float* __restrict__ out, int n) {
    int i = blockIdx.x * blockDim.x + threadIdx.x;
    if (i < n) out[i] = 0.0f;
    if (i < NEXP) { g_cnt[i] = 0; g_fill[i] = 0; }
}

// ---------------- router ----------------
__global__ void router_kernel(const float* __restrict__ x, const float* __restrict__ rw) {
    const int t   = blockIdx.x;
    const int tid = threadIdx.x;
    const float4 xr = reinterpret_cast<const float4*>(x + (size_t)t * DMODEL)[tid];
    float part[NEXP];
#pragma unroll
    for (int e = 0; e < NEXP; ++e) {
        const float4 w = reinterpret_cast<const float4*>(rw + (size_t)e * DMODEL)[tid];
        part[e] = xr.x * w.x + xr.y * w.y + xr.z * w.z + xr.w * w.w;
    }
#pragma unroll
    for (int e = 0; e < NEXP; ++e)
#pragma unroll
        for (int o = 16; o > 0; o >>= 1)
            part[e] += __shfl_down_sync(0xffffffffu, part[e], o);
    __shared__ float sm[NEXP][8];
    const int warp = tid >> 5, lane = tid & 31;
    if (lane == 0)
#pragma unroll
        for (int e = 0; e < NEXP; ++e) sm[e][warp] = part[e];
    __syncthreads();
    if (tid == 0) {
        float lg[NEXP]; float mx = -1e30f;
#pragma unroll
        for (int e = 0; e < NEXP; ++e) {
            float s = 0.f;
#pragma unroll
            for (int w = 0; w < 8; ++w) s += sm[e][w];
            lg[e] = s; mx = fmaxf(mx, s);
        }
        float den = 0.f;
#pragma unroll
        for (int e = 0; e < NEXP; ++e) { lg[e] = expf(lg[e] - mx); den += lg[e]; }
#pragma unroll
        for (int e = 0; e < NEXP; ++e) lg[e] /= den;
        int e0 = 0; float v0 = lg[0];
#pragma unroll
        for (int e = 1; e < NEXP; ++e) if (lg[e] > v0) { v0 = lg[e]; e0 = e; }
        int e1 = -1; float v1 = -1.f;
#pragma unroll
        for (int e = 0; e < NEXP; ++e)
            if (e != e0 && lg[e] > v1) { v1 = lg[e]; e1 = e; }
        const float nrm = v0 + v1;
        g_top_e[t * 2 + 0] = e0; g_top_w[t * 2 + 0] = v0 / nrm;
        g_top_e[t * 2 + 1] = e1; g_top_w[t * 2 + 1] = v1 / nrm;
        atomicAdd(&g_cnt[e0], 1);
        atomicAdd(&g_cnt[e1], 1);
    }
}

__global__ void offsets_kernel() {
    g_off[0] = 0;
    for (int e = 0; e < NEXP; ++e) g_off[e + 1] = g_off[e] + g_cnt[e];
}

__global__ void scatter_kernel() {
    int t = blockIdx.x * blockDim.x + threadIdx.x;
    if (t >= T_TOK) return;
#pragma unroll
    for (int k = 0; k < TOPK; ++k) {
        int e = g_top_e[t * TOPK + k];
        int pos = g_off[e] + atomicAdd(&g_fill[e], 1);
        g_pair_tok[pos]  = t;
        g_pair_gate[pos] = g_top_w[t * TOPK + k];
    }
}

// ---------------- generic fp32 -> bf16 hi/lo split ----------------
__global__ void split_kernel(const float* __restrict__ s, __nv_bfloat16* __restrict__ hi,
                             __nv_bfloat16* __restrict__ lo, int n4) {
    int i = blockIdx.x * blockDim.x + threadIdx.x;
    if (i >= n4) return;
    float4 v = reinterpret_cast<const float4*>(s)[i];
    __nv_bfloat16 h0 = __float2bfloat16(v.x), h1 = __float2bfloat16(v.y);
    __nv_bfloat16 h2 = __float2bfloat16(v.z), h3 = __float2bfloat16(v.w);
    __nv_bfloat162* ph = reinterpret_cast<__nv_bfloat162*>(hi) + i * 2;
    ph[0] = __nv_bfloat162(h0, h1);
    ph[1] = __nv_bfloat162(h2, h3);
    __nv_bfloat162* pl = reinterpret_cast<__nv_bfloat162*>(lo) + i * 2;
    pl[0] = __nv_bfloat162(__float2bfloat16(v.x - __bfloat162float(h0)),
                           __float2bfloat16(v.y - __bfloat162float(h1)));
    pl[1] = __nv_bfloat162(__float2bfloat16(v.z - __bfloat162float(h2)),
                           __float2bfloat16(v.w - __bfloat162float(h3)));
}

// ---------------- w2 transpose + split: w2t[e][d][f] ----------------
__global__ void split_w2t_kernel(const float* __restrict__ w2) {
    __shared__ float t[32][33];
    const int e = blockIdx.z;
    const int f0 = blockIdx.x * 32, d0 = blockIdx.y * 32;
    const int tx = threadIdx.x, ty = threadIdx.y;   // 32 x 8
#pragma unroll
    for (int j = 0; j < 4; ++j)
        t[ty + j * 8][tx] = w2[((size_t)e * FFN + f0 + ty + j * 8) * DMODEL + d0 + tx];
    __syncthreads();
#pragma unroll
    for (int j = 0; j < 4; ++j) {
        const int dl = ty + j * 8;
        float v = t[tx][dl];
        __nv_bfloat16 hi = __float2bfloat16(v);
        size_t o = ((size_t)e * DMODEL + d0 + dl) * FFN + f0 + tx;
        g_w2t_hi[o] = hi;
        g_w2t_lo[o] = __float2bfloat16(v - __bfloat162float(hi));
    }
}

// ---------------- GEMM tile constants ----------------
#define STG_SZ 32768
#define OFF_AH 0
#define OFF_AL 8192
#define OFF_BH 16384
#define OFF_BL 24576

// ============ GEMM1 (fused): h = silu(x@w1^T)*(x@v1^T), R4 staging ============
// Block: 128 pairs x 64 F cols. B smem rows 0-63 = w1 tile, 64-127 = v1 tile.
// Warps 0-3 (mat=0) -> w1 product; warps 4-7 (mat=1) -> v1 product.
__global__ void __launch_bounds__(256, 1) gemm1_kernel() {
    extern __shared__ char smem[];
    __shared__ int toks[128];
    const unsigned sb = smem_u32(smem);
    const int tid = threadIdx.x, lane = tid & 31, wid = tid >> 5;
    const int n0 = blockIdx.x * 64;
    const int e = blockIdx.y;
    const int off = g_off[e], cnt = g_cnt[e];

    const int mat = wid >> 2, wm = (wid >> 1) & 1, wn = wid & 1;
    unsigned aoffs[2][4], boffs[2][2];
#pragma unroll
    for (int ks = 0; ks < 2; ++ks) {
#pragma unroll
        for (int m = 0; m < 4; ++m) {
            int r = wm * 64 + m * 16 + ((lane >> 3) & 1) * 8 + (lane & 7);
            aoffs[ks][m] = swz(r, ((lane >> 4) << 4) + ks * 32);
        }
#pragma unroll
        for (int np = 0; np < 2; ++np) {
            int r = mat * 64 + wn * 32 + np * 16 + ((lane >> 4) << 3) + (lane & 7);
            boffs[ks][np] = swz(r, (((lane >> 3) & 1) << 4) + ks * 32);
        }
    }
    const int prow0 = tid >> 2;
    const int pc16 = (tid & 3) * 16;  // byte col
    const int pc8  = (tid & 3) * 8;   // element col
    unsigned soffs[2];
    soffs[0] = swz(prow0, pc16);
    soffs[1] = swz(prow0 + 64, pc16);
    const size_t wbase = ((size_t)e * FFN + n0 + prow0) * DMODEL + pc8;

    for (int mt = blockIdx.z; mt * 128 < cnt; mt += gridDim.z) {
        if (tid < 128) {
            int r = mt * 128 + tid;
            toks[tid] = (r < cnt) ? g_pair_tok[off + r] : -1;
        }
        __syncthreads();
        float acc[4][4][4];
#pragma unroll
        for (int m = 0; m < 4; ++m)
#pragma unroll
            for (int n = 0; n < 4; ++n)
#pragma unroll
                for (int q = 0; q < 4; ++q) acc[m][n][q] = 0.f;

        uint4 rAh[2], rAl[2], rBh[2], rBl[2];
        const uint4 z4 = make_uint4(0, 0, 0, 0);
        // B: j=0 -> w1 tile, j=1 -> v1 tile (same rows n0+prow0)
#define G1_LDG(K0)                                                                  \
        {                                                                           \
            _Pragma("unroll")                                                       \
            for (int j = 0; j < 2; ++j) {                                           \
                const int row = prow0 + j * 64;                                     \
                const int tok = toks[row];                                          \
                if (tok >= 0) {                                                     \
                    size_t ao = (size_t)tok * DMODEL + (K0) + pc8;                  \
                    rAh[j] = *reinterpret_cast<const uint4*>(g_xs_hi + ao);         \
                    rAl[j] = *reinterpret_cast<const uint4*>(g_xs_lo + ao);         \
                } else { rAh[j] = z4; rAl[j] = z4; }                                \
            }                                                                       \
            rBh[0] = *reinterpret_cast<const uint4*>(g_w1_hi + wbase + (K0));       \
            rBl[0] = *reinterpret_cast<const uint4*>(g_w1_lo + wbase + (K0));       \
            rBh[1] = *reinterpret_cast<const uint4*>(g_v1_hi + wbase + (K0));       \
            rBl[1] = *reinterpret_cast<const uint4*>(g_v1_lo + wbase + (K0));       \
        }
        G1_LDG(0)
        for (int c = 0; c < DMODEL / 32; ++c) {
            const unsigned so = (unsigned)(c & 1) * STG_SZ;
#pragma unroll
            for (int j = 0; j < 2; ++j) {
                *reinterpret_cast<uint4*>(smem + so + OFF_AH + soffs[j]) = rAh[j];
                *reinterpret_cast<uint4*>(smem + so + OFF_AL + soffs[j]) = rAl[j];
                *reinterpret_cast<uint4*>(smem + so + OFF_BH + soffs[j]) = rBh[j];
                *reinterpret_cast<uint4*>(smem + so + OFF_BL + soffs[j]) = rBl[j];
            }
            if (c + 1 < DMODEL / 32) G1_LDG((c + 1) * 32)
            __syncthreads();
#pragma unroll
            for (int ks = 0; ks < 2; ++ks) {
                unsigned aH[4][4], aL[4][4], bH[2][4], bL[2][4];
#pragma unroll
                for (int m = 0; m < 4; ++m) {
                    ldm4(aH[m], sb + so + OFF_AH + aoffs[ks][m]);
                    ldm4(aL[m], sb + so + OFF_AL + aoffs[ks][m]);
                }
#pragma unroll
                for (int np = 0; np < 2; ++np) {
                    ldm4(bH[np], sb + so + OFF_BH + boffs[ks][np]);
                    ldm4(bL[np], sb + so + OFF_BL + boffs[ks][np]);
                }
#pragma unroll
                for (int np = 0; np < 2; ++np)
#pragma unroll
                    for (int hf = 0; hf < 2; ++hf)
#pragma unroll
                        for (int m = 0; m < 4; ++m)
                            mma16816(acc[m][np * 2 + hf], aH[m], &bH[np][hf * 2]);
#pragma unroll
                for (int np = 0; np < 2; ++np)
#pragma unroll
                    for (int hf = 0; hf < 2; ++hf)
#pragma unroll
                        for (int m = 0; m < 4; ++m)
                            mma16816(acc[m][np * 2 + hf], aH[m], &bL[np][hf * 2]);
#pragma unroll
                for (int np = 0; np < 2; ++np)
#pragma unroll
                    for (int hf = 0; hf < 2; ++hf)
#pragma unroll
                        for (int m = 0; m < 4; ++m)
                            mma16816(acc[m][np * 2 + hf], aL[m], &bH[np][hf * 2]);
            }
            __syncthreads();
        }
        // ---- epilogue: v1 warps stage tile via smem; w1 warps SwiGLU + write h ----
        float (*exch)[68] = reinterpret_cast<float (*)[68]>(smem);
        if (mat == 1) {
#pragma unroll
            for (int m = 0; m < 4; ++m)
#pragma unroll
                for (int hf = 0; hf < 2; ++hf) {
                    const int row = wm * 64 + m * 16 + (lane >> 2) + hf * 8;
#pragma unroll
                    for (int n = 0; n < 4; ++n) {
                        const int col = wn * 32 + n * 8 + (lane & 3) * 2;
                        exch[row][col]     = acc[m][n][hf * 2];
                        exch[row][col + 1] = acc[m][n][hf * 2 + 1];
                    }
                }
        }
        __syncthreads();
        if (mat == 0) {
#pragma unroll
            for (int m = 0; m < 4; ++m)
#pragma unroll
                for (int hf = 0; hf < 2; ++hf) {
                    const int row = wm * 64 + m * 16 + (lane >> 2) + hf * 8;
                    const int rl = mt * 128 + row;
                    if (rl < cnt) {
                        const size_t rbase = (size_t)(off + rl) * FFN + n0;
#pragma unroll
                        for (int n = 0; n < 4; ++n) {
                            const int col = wn * 32 + n * 8 + (lane & 3) * 2;
                            const float g0 = acc[m][n][hf * 2];
                            const float g1 = acc[m][n][hf * 2 + 1];
                            const float l0 = exch[row][col];
                            const float l1 = exch[row][col + 1];
                            const float h0 = g0 / (1.f + __expf(-g0)) * l0;
                            const float h1 = g1 / (1.f + __expf(-g1)) * l1;
                            float ra, rb;
                            const unsigned hp = bf2_hi(h0, h1, ra, rb);
                            const unsigned lp = bf2(ra, rb);
                            *reinterpret_cast<unsigned*>(
                                reinterpret_cast<char*>(g_h_hi) + (rbase + col) * 2) = hp;
                            *reinterpret_cast<unsigned*>(
                                reinterpret_cast<char*>(g_h_lo) + (rbase + col) * 2) = lp;
                        }
                    }
                }
        }
        __syncthreads();
    }
}

// ============ GEMM2: out += gate * (h @ w2t^T)  (R4 verbatim) ============
__global__ void __launch_bounds__(256, 1) gemm2_kernel(float* __restrict__ out) {
    extern __shared__ char smem[];
    const unsigned sb = smem_u32(smem);
    const int tid = threadIdx.x, lane = tid & 31, wid = tid >> 5;
    const int n0 = blockIdx.x * 128;
    const int e = blockIdx.y;
    const int off = g_off[e], cnt = g_cnt[e];

    const int wm = wid & 1, wn = wid >> 1;
    unsigned aoffs[2][4], boffs[2][2];
#pragma unroll
    for (int ks = 0; ks < 2; ++ks) {
#pragma unroll
        for (int m = 0; m < 4; ++m) {
            int r = wm * 64 + m * 16 + ((lane >> 3) & 1) * 8 + (lane & 7);
            aoffs[ks][m] = swz(r, ((lane >> 4) << 4) + ks * 32);
        }
#pragma unroll
        for (int np = 0; np < 2; ++np) {
            int r = wn * 32 + np * 16 + ((lane >> 4) << 3) + (lane & 7);
            boffs[ks][np] = swz(r, (((lane >> 3) & 1) << 4) + ks * 32);
        }
    }
    const int prow0 = tid >> 2;
    const int pc16 = (tid & 3) * 16;
    const int pc8  = (tid & 3) * 8;
    unsigned soffs[2];
    soffs[0] = swz(prow0, pc16);
    soffs[1] = swz(prow0 + 64, pc16);

    for (int mt = blockIdx.z; mt * 128 < cnt; mt += gridDim.z) {
        float acc[4][4][4];
#pragma unroll
        for (int m = 0; m < 4; ++m)
#pragma unroll
            for (int n = 0; n < 4; ++n)
#pragma unroll
                for (int q = 0; q < 4; ++q) acc[m][n][q] = 0.f;

        uint4 rAh[2], rAl[2], rBh[2], rBl[2];
        const uint4 z4 = make_uint4(0, 0, 0, 0);
#define G2_LDG(K0)                                                                  \
        {                                                                           \
            _Pragma("unroll")                                                       \
            for (int j = 0; j < 2; ++j) {                                           \
                const int row = prow0 + j * 64;                                     \
                const int rl = mt * 128 + row;                                      \
                if (rl < cnt) {                                                     \
                    size_t ao = (size_t)(off + rl) * FFN + (K0) + pc8;              \
                    rAh[j] = *reinterpret_cast<const uint4*>(g_h_hi + ao);          \
                    rAl[j] = *reinterpret_cast<const uint4*>(g_h_lo + ao);          \
                } else { rAh[j] = z4; rAl[j] = z4; }                                \
                size_t bo = ((size_t)e * DMODEL + n0 + row) * FFN + (K0) + pc8;     \
                rBh[j] = *reinterpret_cast<const uint4*>(g_w2t_hi + bo);            \
                rBl[j] = *reinterpret_cast<const uint4*>(g_w2t_lo + bo);            \
            }                                                                       \
        }
        G2_LDG(0)
        for (int c = 0; c < FFN / 32; ++c) {
            const unsigned so = (unsigned)(c & 1) * STG_SZ;
#pragma unroll
            for (int j = 0; j < 2; ++j) {
                *reinterpret_cast<uint4*>(smem + so + OFF_AH + soffs[j]) = rAh[j];
                *reinterpret_cast<uint4*>(smem + so + OFF_AL + soffs[j]) = rAl[j];
                *reinterpret_cast<uint4*>(smem + so + OFF_BH + soffs[j]) = rBh[j];
                *reinterpret_cast<uint4*>(smem + so + OFF_BL + soffs[j]) = rBl[j];
            }
            if (c + 1 < FFN / 32) G2_LDG((c + 1) * 32)
            __syncthreads();
#pragma unroll
            for (int ks = 0; ks < 2; ++ks) {
                unsigned aH[4][4], aL[4][4], bH[2][4], bL[2][4];
#pragma unroll
                for (int m = 0; m < 4; ++m) {
                    ldm4(aH[m], sb + so + OFF_AH + aoffs[ks][m]);
                    ldm4(aL[m], sb + so + OFF_AL + aoffs[ks][m]);
                }
#pragma unroll
                for (int np = 0; np < 2; ++np) {
                    ldm4(bH[np], sb + so + OFF_BH + boffs[ks][np]);
                    ldm4(bL[np], sb + so + OFF_BL + boffs[ks][np]);
                }
#pragma unroll
                for (int np = 0; np < 2; ++np)
#pragma unroll
                    for (int hf = 0; hf < 2; ++hf)
#pragma unroll
                        for (int m = 0; m < 4; ++m)
                            mma16816(acc[m][np * 2 + hf], aH[m], &bH[np][hf * 2]);
#pragma unroll
                for (int np = 0; np < 2; ++np)
#pragma unroll
                    for (int hf = 0; hf < 2; ++hf)
#pragma unroll
                        for (int m = 0; m < 4; ++m)
                            mma16816(acc[m][np * 2 + hf], aH[m], &bL[np][hf * 2]);
#pragma unroll
                for (int np = 0; np < 2; ++np)
#pragma unroll
                    for (int hf = 0; hf < 2; ++hf)
#pragma unroll
                        for (int m = 0; m < 4; ++m)
                            mma16816(acc[m][np * 2 + hf], aL[m], &bH[np][hf * 2]);
            }
            __syncthreads();
        }
        // epilogue: gate-scaled atomic combine (2 adds per output elem total)
#pragma unroll
        for (int m = 0; m < 4; ++m)
#pragma unroll
            for (int hf = 0; hf < 2; ++hf) {
                const int rl = mt * 128 + wm * 64 + m * 16 + (lane >> 2) + hf * 8;
                if (rl < cnt) {
                    const int   tok = g_pair_tok[off + rl];
                    const float gt  = g_pair_gate[off + rl];
                    float* dst = out + (size_t)tok * DMODEL + n0 + wn * 32 + (lane & 3) * 2;
#pragma unroll
                    for (int n = 0; n < 4; ++n) {
                        atomicAdd(dst + n * 8 + 0, gt * acc[m][n][hf * 2]);
                        atomicAdd(dst + n * 8 + 1, gt * acc[m][n][hf * 2 + 1]);
                    }
                }
            }
        __syncthreads();
    }
}

// ---------------- launch ----------------
extern "C" void kernel_launch(void* const* d_in, const int* in_sizes, int n_in,
                              void* d_out, int out_size) {
    const float* x  = (const float*)d_in[0];
    const float* w1 = (const float*)d_in[1];
    const float* v1 = (const float*)d_in[2];
    const float* w2 = (const float*)d_in[3];
    const float* rw = (const float*)d_in[4];
    float* out = (float*)d_out;

    cudaFuncSetAttribute(gemm1_kernel, cudaFuncAttributeMaxDynamicSharedMemorySize, 2 * STG_SZ);
    cudaFuncSetAttribute(gemm2_kernel, cudaFuncAttributeMaxDynamicSharedMemorySize, 2 * STG_SZ);

    init_kernel<<<(T_TOK * DMODEL + 255) / 256, 256>>>(out, T_TOK * DMODEL);
    router_kernel<<<T_TOK, 256>>>(x, rw);
    offsets_kernel<<<1, 1>>>();
    scatter_kernel<<<(T_TOK + 255) / 256, 256>>>();

    __nv_bfloat16 *xs_hi, *xs_lo, *w1_hi, *w1_lo, *v1_hi, *v1_lo;
    cudaGetSymbolAddress((void**)&xs_hi, g_xs_hi);
    cudaGetSymbolAddress((void**)&xs_lo, g_xs_lo);
    cudaGetSymbolAddress((void**)&w1_hi, g_w1_hi);
    cudaGetSymbolAddress((void**)&w1_lo, g_w1_lo);
    cudaGetSymbolAddress((void**)&v1_hi, g_v1_hi);
    cudaGetSymbolAddress((void**)&v1_lo, g_v1_lo);

    const int nx4 = T_TOK * DMODEL / 4;
    const int nw4 = NEXP * FFN * DMODEL / 4;
    split_kernel<<<(nx4 + 255) / 256, 256>>>(x, xs_hi, xs_lo, nx4);
    split_kernel<<<(nw4 + 255) / 256, 256>>>(w1, w1_hi, w1_lo, nw4);
    split_kernel<<<(nw4 + 255) / 256, 256>>>(v1, v1_hi, v1_lo, nw4);
    split_w2t_kernel<<<dim3(FFN / 32, DMODEL / 32, NEXP), dim3(32, 8)>>>(w2);

    gemm1_kernel<<<dim3(FFN / 64, NEXP, 4), 256, 2 * STG_SZ>>>();
    gemm2_kernel<<<dim3(DMODEL / 128, NEXP, 8), 256, 2 * STG_SZ>>>(out);
}

// round 7
// speedup vs baseline: 1.2985x; 1.2985x over previous
#include <cuda_runtime.h>
#include <cuda_fp16.h>

#define T_TOK 4096
#define DMODEL 1024
#define NEXP 8
#define FFN 2048
#define TOPK 2
#define NPAIR (T_TOK * TOPK)

// ---------------- device scratch ----------------
__device__ int   g_cnt[NEXP];        // zero at module load; scatter re-zeros at end
__device__ int   g_off[NEXP + 1];
__device__ int   g_fill[NEXP];
__device__ int   g_pair_tok[NPAIR];
__device__ float g_pair_gate[NPAIR];
__device__ int   g_top_e[NPAIR];
__device__ float g_top_w[NPAIR];

__device__ __align__(16) __half g_xs_hi[(size_t)T_TOK * DMODEL];
__device__ __align__(16) __half g_xs_lo[(size_t)T_TOK * DMODEL];
__device__ __align__(16) __half g_w1_hi[(size_t)NEXP * FFN * DMODEL];
__device__ __align__(16) __half g_v1_hi[(size_t)NEXP * FFN * DMODEL];
__device__ __align__(16) __half g_w2t_hi[(size_t)NEXP * DMODEL * FFN];
__device__ __align__(16) float  g_g[(size_t)NPAIR * FFN];
__device__ __align__(16) float  g_l[(size_t)NPAIR * FFN];
__device__ __align__(16) __half g_h_hi[(size_t)NPAIR * FFN];
__device__ __align__(16) __half g_h_lo[(size_t)NPAIR * FFN];

// ---------------- helpers ----------------
__device__ __forceinline__ unsigned smem_u32(const void* p) {
    unsigned a;
    asm("{ .reg .u64 t; cvta.to.shared.u64 t, %1; cvt.u32.u64 %0, t; }"
        : "=r"(a) : "l"(p));
    return a;
}
// swizzled byte offset in a [rows][32 f16] tile (64B rows); c must be < 64
__device__ __forceinline__ unsigned swz(int row, int c) {
    return (unsigned)(row * 64 + (c ^ ((row & 6) << 3)));
}
__device__ __forceinline__ void ldm4(unsigned* r, unsigned addr) {
    asm volatile("ldmatrix.sync.aligned.m8n8.x4.shared.b16 {%0,%1,%2,%3}, [%4];"
                 : "=r"(r[0]), "=r"(r[1]), "=r"(r[2]), "=r"(r[3]) : "r"(addr));
}
__device__ __forceinline__ void mma16816(float* c, const unsigned* a, const unsigned* b) {
    asm volatile(
        "mma.sync.aligned.m16n8k16.row.col.f32.f16.f16.f32 "
        "{%0,%1,%2,%3}, {%4,%5,%6,%7}, {%8,%9}, {%0,%1,%2,%3};"
        : "+f"(c[0]), "+f"(c[1]), "+f"(c[2]), "+f"(c[3])
        : "r"(a[0]), "r"(a[1]), "r"(a[2]), "r"(a[3]), "r"(b[0]), "r"(b[1]));
}
__device__ __forceinline__ unsigned packh(__half a, __half b) {
    __half2 t = __halves2half2(a, b);
    return *reinterpret_cast<unsigned*>(&t);
}
__device__ __forceinline__ void split2h(float a, float b, unsigned& hi, unsigned& lo) {
    __half ha = __float2half_rn(a), hb = __float2half_rn(b);
    __half la = __float2half_rn(a - __half2float(ha));
    __half lb = __float2half_rn(b - __half2float(hb));
    hi = packh(ha, hb);
    lo = packh(la, lb);
}

// ---------------- router (also zeroes out) ----------------
__global__ void router_kernel(const float* __restrict__ x, const float* __restrict__ rw,
                              float* __restrict__ out) {
    const int t   = blockIdx.x;
    const int tid = threadIdx.x;
    reinterpret_cast<float4*>(out + (size_t)t * DMODEL)[tid] = make_float4(0.f, 0.f, 0.f, 0.f);

    const float4 xr = reinterpret_cast<const float4*>(x + (size_t)t * DMODEL)[tid];
    float part[NEXP];
#pragma unroll
    for (int e = 0; e < NEXP; ++e) {
        const float4 w = reinterpret_cast<const float4*>(rw + (size_t)e * DMODEL)[tid];
        part[e] = xr.x * w.x + xr.y * w.y + xr.z * w.z + xr.w * w.w;
    }
#pragma unroll
    for (int e = 0; e < NEXP; ++e)
#pragma unroll
        for (int o = 16; o > 0; o >>= 1)
            part[e] += __shfl_down_sync(0xffffffffu, part[e], o);
    __shared__ float sm[NEXP][8];
    const int warp = tid >> 5, lane = tid & 31;
    if (lane == 0)
#pragma unroll
        for (int e = 0; e < NEXP; ++e) sm[e][warp] = part[e];
    __syncthreads();
    if (tid == 0) {
        float lg[NEXP]; float mx = -1e30f;
#pragma unroll
        for (int e = 0; e < NEXP; ++e) {
            float s = 0.f;
#pragma unroll
            for (int w = 0; w < 8; ++w) s += sm[e][w];
            lg[e] = s; mx = fmaxf(mx, s);
        }
        float den = 0.f;
#pragma unroll
        for (int e = 0; e < NEXP; ++e) { lg[e] = expf(lg[e] - mx); den += lg[e]; }
#pragma unroll
        for (int e = 0; e < NEXP; ++e) lg[e] /= den;
        int e0 = 0; float v0 = lg[0];
#pragma unroll
        for (int e = 1; e < NEXP; ++e) if (lg[e] > v0) { v0 = lg[e]; e0 = e; }
        int e1 = -1; float v1 = -1.f;
#pragma unroll
        for (int e = 0; e < NEXP; ++e)
            if (e != e0 && lg[e] > v1) { v1 = lg[e]; e1 = e; }
        const float nrm = v0 + v1;
        g_top_e[t * 2 + 0] = e0; g_top_w[t * 2 + 0] = v0 / nrm;
        g_top_e[t * 2 + 1] = e1; g_top_w[t * 2 + 1] = v1 / nrm;
        atomicAdd(&g_cnt[e0], 1);
        atomicAdd(&g_cnt[e1], 1);
    }
}

// ---- scatter (single block): offsets + pair lists + counter reset for replay ----
__global__ void scatter_kernel() {
    if (threadIdx.x == 0) {
        int r = 0;
        g_off[0] = 0;
        for (int e = 0; e < NEXP; ++e) { r += g_cnt[e]; g_off[e + 1] = r; }
    }
    __syncthreads();
    for (int t = threadIdx.x; t < T_TOK; t += blockDim.x) {
#pragma unroll
        for (int k = 0; k < TOPK; ++k) {
            int e = g_top_e[t * TOPK + k];
            int pos = g_off[e] + atomicAdd(&g_fill[e], 1);
            g_pair_tok[pos]  = t;
            g_pair_gate[pos] = g_top_w[t * TOPK + k];
        }
    }
    __syncthreads();
    if (threadIdx.x < NEXP) { g_cnt[threadIdx.x] = 0; g_fill[threadIdx.x] = 0; }
}

// ---------------- x split: fp32 -> fp16 hi/lo ----------------
__global__ void split_x_kernel(const float* __restrict__ s, int n4) {
    int i = blockIdx.x * blockDim.x + threadIdx.x;
    if (i >= n4) return;
    float4 v = reinterpret_cast<const float4*>(s)[i];
    unsigned h0, l0, h1, l1;
    split2h(v.x, v.y, h0, l0);
    split2h(v.z, v.w, h1, l1);
    reinterpret_cast<uint2*>(g_xs_hi)[i] = make_uint2(h0, h1);
    reinterpret_cast<uint2*>(g_xs_lo)[i] = make_uint2(l0, l1);
}

// ---------------- w1+v1 convert: fp32 -> fp16 (hi only), one launch ----------------
__global__ void split_w_kernel(const float* __restrict__ w1, const float* __restrict__ v1,
                               int n4) {
    int i = blockIdx.x * blockDim.x + threadIdx.x;
    if (i >= n4) return;
    const float* s = blockIdx.y ? v1 : w1;
    __half* d = blockIdx.y ? g_v1_hi : g_w1_hi;
    float4 v = reinterpret_cast<const float4*>(s)[i];
    unsigned p0 = packh(__float2half_rn(v.x), __float2half_rn(v.y));
    unsigned p1 = packh(__float2half_rn(v.z), __float2half_rn(v.w));
    reinterpret_cast<uint2*>(d)[i] = make_uint2(p0, p1);
}

// ---------------- w2 transpose + fp16 convert: w2t[e][d][f] ----------------
__global__ void split_w2t_kernel(const float* __restrict__ w2) {
    __shared__ float t[32][33];
    const int e = blockIdx.z;
    const int f0 = blockIdx.x * 32, d0 = blockIdx.y * 32;
    const int tx = threadIdx.x, ty = threadIdx.y;   // 32 x 8
#pragma unroll
    for (int j = 0; j < 4; ++j)
        t[ty + j * 8][tx] = w2[((size_t)e * FFN + f0 + ty + j * 8) * DMODEL + d0 + tx];
    __syncthreads();
#pragma unroll
    for (int j = 0; j < 4; ++j) {
        const int dl = ty + j * 8;
        g_w2t_hi[((size_t)e * DMODEL + d0 + dl) * FFN + f0 + tx] =
            __float2half_rn(t[tx][dl]);
    }
}

// ---------------- SwiGLU + split h -> fp16 hi/lo ----------------
__global__ void h_split_kernel(int n4) {
    int i = blockIdx.x * blockDim.x + threadIdx.x;
    if (i >= n4) return;
    float4 g = reinterpret_cast<const float4*>(g_g)[i];
    float4 l = reinterpret_cast<const float4*>(g_l)[i];
    float4 h;
    h.x = g.x / (1.f + __expf(-g.x)) * l.x;
    h.y = g.y / (1.f + __expf(-g.y)) * l.y;
    h.z = g.z / (1.f + __expf(-g.z)) * l.z;
    h.w = g.w / (1.f + __expf(-g.w)) * l.w;
    unsigned h0, l0, h1, l1;
    split2h(h.x, h.y, h0, l0);
    split2h(h.z, h.w, h1, l1);
    reinterpret_cast<uint2*>(g_h_hi)[i] = make_uint2(h0, h1);
    reinterpret_cast<uint2*>(g_h_lo)[i] = make_uint2(l0, l1);
}

// ---------------- GEMM tile constants ----------------
#define STG_SZ 24576
#define OFF_AH 0
#define OFF_AL 8192
#define OFF_BH 16384

// ---------------- GEMM1: g/l = x @ {w1,v1}^T (per-expert gathered rows) ----------
__global__ void __launch_bounds__(256, 1) gemm1_kernel() {
    extern __shared__ char smem[];
    __shared__ int toks[128];
    const unsigned sb = smem_u32(smem);
    const int tid = threadIdx.x, lane = tid & 31, wid = tid >> 5;
    const int bx = blockIdx.x;
    const int sel = bx >> 4;
    const int n0 = (bx & 15) * 128;
    const int e = blockIdx.y;
    const int off = g_off[e], cnt = g_off[e + 1] - off;
    const __half* __restrict__ Bh = sel ? g_v1_hi : g_w1_hi;
    float* __restrict__ outp = sel ? g_l : g_g;

    const int wm = wid & 1, wn = wid >> 1;
    unsigned aoffs[2][4], boffs[2][2];
#pragma unroll
    for (int ks = 0; ks < 2; ++ks) {
#pragma unroll
        for (int m = 0; m < 4; ++m) {
            int r = wm * 64 + m * 16 + ((lane >> 3) & 1) * 8 + (lane & 7);
            aoffs[ks][m] = swz(r, ((lane >> 4) << 4) + ks * 32);
        }
#pragma unroll
        for (int np = 0; np < 2; ++np) {
            int r = wn * 32 + np * 16 + ((lane >> 4) << 3) + (lane & 7);
            boffs[ks][np] = swz(r, (((lane >> 3) & 1) << 4) + ks * 32);
        }
    }
    const int prow0 = tid >> 2;
    const int pc16 = (tid & 3) * 16;  // byte col
    const int pc8  = (tid & 3) * 8;   // element col
    unsigned soffs[2];
    soffs[0] = swz(prow0, pc16);
    soffs[1] = swz(prow0 + 64, pc16);

    for (int mt = blockIdx.z; mt * 128 < cnt; mt += gridDim.z) {
        if (tid < 128) {
            int r = mt * 128 + tid;
            toks[tid] = (r < cnt) ? g_pair_tok[off + r] : -1;
        }
        __syncthreads();
        float acc[4][4][4];
#pragma unroll
        for (int m = 0; m < 4; ++m)
#pragma unroll
            for (int n = 0; n < 4; ++n)
#pragma unroll
                for (int q = 0; q < 4; ++q) acc[m][n][q] = 0.f;

        uint4 rAh[2], rAl[2], rBh[2];
        const uint4 z4 = make_uint4(0, 0, 0, 0);
#define G1_LDG(K0)                                                                  \
        {                                                                           \
            _Pragma("unroll")                                                       \
            for (int j = 0; j < 2; ++j) {                                           \
                const int row = prow0 + j * 64;                                     \
                const int tok = toks[row];                                          \
                if (tok >= 0) {                                                     \
                    size_t ao = (size_t)tok * DMODEL + (K0) + pc8;                  \
                    rAh[j] = *reinterpret_cast<const uint4*>(g_xs_hi + ao);         \
                    rAl[j] = *reinterpret_cast<const uint4*>(g_xs_lo + ao);         \
                } else { rAh[j] = z4; rAl[j] = z4; }                                \
                size_t bo = ((size_t)e * FFN + n0 + row) * DMODEL + (K0) + pc8;     \
                rBh[j] = *reinterpret_cast<const uint4*>(Bh + bo);                  \
            }                                                                       \
        }
        G1_LDG(0)
        for (int c = 0; c < DMODEL / 32; ++c) {
            const unsigned so = (unsigned)(c & 1) * STG_SZ;
#pragma unroll
            for (int j = 0; j < 2; ++j) {
                *reinterpret_cast<uint4*>(smem + so + OFF_AH + soffs[j]) = rAh[j];
                *reinterpret_cast<uint4*>(smem + so + OFF_AL + soffs[j]) = rAl[j];
                *reinterpret_cast<uint4*>(smem + so + OFF_BH + soffs[j]) = rBh[j];
            }
            if (c + 1 < DMODEL / 32) G1_LDG((c + 1) * 32)
            __syncthreads();
#pragma unroll
            for (int ks = 0; ks < 2; ++ks) {
                unsigned aH[4][4], aL[4][4], bH[2][4];
#pragma unroll
                for (int m = 0; m < 4; ++m) {
                    ldm4(aH[m], sb + so + OFF_AH + aoffs[ks][m]);
                    ldm4(aL[m], sb + so + OFF_AL + aoffs[ks][m]);
                }
#pragma unroll
                for (int np = 0; np < 2; ++np)
                    ldm4(bH[np], sb + so + OFF_BH + boffs[ks][np]);
#pragma unroll
                for (int np = 0; np < 2; ++np)
#pragma unroll
                    for (int hf = 0; hf < 2; ++hf)
#pragma unroll
                        for (int m = 0; m < 4; ++m)
                            mma16816(acc[m][np * 2 + hf], aH[m], &bH[np][hf * 2]);
#pragma unroll
                for (int np = 0; np < 2; ++np)
#pragma unroll
                    for (int hf = 0; hf < 2; ++hf)
#pragma unroll
                        for (int m = 0; m < 4; ++m)
                            mma16816(acc[m][np * 2 + hf], aL[m], &bH[np][hf * 2]);
            }
            __syncthreads();
        }
        // epilogue: write g or l (fp32)
#pragma unroll
        for (int m = 0; m < 4; ++m)
#pragma unroll
            for (int hf = 0; hf < 2; ++hf) {
                const int rl = mt * 128 + wm * 64 + m * 16 + (lane >> 2) + hf * 8;
                if (rl < cnt) {
                    float* dst = outp + (size_t)(off + rl) * FFN + n0 + wn * 32 + (lane & 3) * 2;
#pragma unroll
                    for (int n = 0; n < 4; ++n) {
                        float2 v = make_float2(acc[m][n][hf * 2], acc[m][n][hf * 2 + 1]);
                        *reinterpret_cast<float2*>(dst + n * 8) = v;
                    }
                }
            }
        __syncthreads();
    }
}

// ---------------- GEMM2: out += gate * (h @ w2t^T) ----------------
__global__ void __launch_bounds__(256, 1) gemm2_kernel(float* __restrict__ out) {
    extern __shared__ char smem[];
    const unsigned sb = smem_u32(smem);
    const int tid = threadIdx.x, lane = tid & 31, wid = tid >> 5;
    const int n0 = blockIdx.x * 128;
    const int e = blockIdx.y;
    const int off = g_off[e], cnt = g_off[e + 1] - off;

    const int wm = wid & 1, wn = wid >> 1;
    unsigned aoffs[2][4], boffs[2][2];
#pragma unroll
    for (int ks = 0; ks < 2; ++ks) {
#pragma unroll
        for (int m = 0; m < 4; ++m) {
            int r = wm * 64 + m * 16 + ((lane >> 3) & 1) * 8 + (lane & 7);
            aoffs[ks][m] = swz(r, ((lane >> 4) << 4) + ks * 32);
        }
#pragma unroll
        for (int np = 0; np < 2; ++np) {
            int r = wn * 32 + np * 16 + ((lane >> 4) << 3) + (lane & 7);
            boffs[ks][np] = swz(r, (((lane >> 3) & 1) << 4) + ks * 32);
        }
    }
    const int prow0 = tid >> 2;
    const int pc16 = (tid & 3) * 16;
    const int pc8  = (tid & 3) * 8;
    unsigned soffs[2];
    soffs[0] = swz(prow0, pc16);
    soffs[1] = swz(prow0 + 64, pc16);

    for (int mt = blockIdx.z; mt * 128 < cnt; mt += gridDim.z) {
        float acc[4][4][4];
#pragma unroll
        for (int m = 0; m < 4; ++m)
#pragma unroll
            for (int n = 0; n < 4; ++n)
#pragma unroll
                for (int q = 0; q < 4; ++q) acc[m][n][q] = 0.f;

        uint4 rAh[2], rAl[2], rBh[2];
        const uint4 z4 = make_uint4(0, 0, 0, 0);
#define G2_LDG(K0)                                                                  \
        {                                                                           \
            _Pragma("unroll")                                                       \
            for (int j = 0; j < 2; ++j) {                                           \
                const int row = prow0 + j * 64;                                     \
                const int rl = mt * 128 + row;                                      \
                if (rl < cnt) {                                                     \
                    size_t ao = (size_t)(off + rl) * FFN + (K0) + pc8;              \
                    rAh[j] = *reinterpret_cast<const uint4*>(g_h_hi + ao);          \
                    rAl[j] = *reinterpret_cast<const uint4*>(g_h_lo + ao);          \
                } else { rAh[j] = z4; rAl[j] = z4; }                                \
                size_t bo = ((size_t)e * DMODEL + n0 + row) * FFN + (K0) + pc8;     \
                rBh[j] = *reinterpret_cast<const uint4*>(g_w2t_hi + bo);            \
            }                                                                       \
        }
        G2_LDG(0)
        for (int c = 0; c < FFN / 32; ++c) {
            const unsigned so = (unsigned)(c & 1) * STG_SZ;
#pragma unroll
            for (int j = 0; j < 2; ++j) {
                *reinterpret_cast<uint4*>(smem + so + OFF_AH + soffs[j]) = rAh[j];
                *reinterpret_cast<uint4*>(smem + so + OFF_AL + soffs[j]) = rAl[j];
                *reinterpret_cast<uint4*>(smem + so + OFF_BH + soffs[j]) = rBh[j];
            }
            if (c + 1 < FFN / 32) G2_LDG((c + 1) * 32)
            __syncthreads();
#pragma unroll
            for (int ks = 0; ks < 2; ++ks) {
                unsigned aH[4][4], aL[4][4], bH[2][4];
#pragma unroll
                for (int m = 0; m < 4; ++m) {
                    ldm4(aH[m], sb + so + OFF_AH + aoffs[ks][m]);
                    ldm4(aL[m], sb + so + OFF_AL + aoffs[ks][m]);
                }
#pragma unroll
                for (int np = 0; np < 2; ++np)
                    ldm4(bH[np], sb + so + OFF_BH + boffs[ks][np]);
#pragma unroll
                for (int np = 0; np < 2; ++np)
#pragma unroll
                    for (int hf = 0; hf < 2; ++hf)
#pragma unroll
                        for (int m = 0; m < 4; ++m)
                            mma16816(acc[m][np * 2 + hf], aH[m], &bH[np][hf * 2]);
#pragma unroll
                for (int np = 0; np < 2; ++np)
#pragma unroll
                    for (int hf = 0; hf < 2; ++hf)
#pragma unroll
                        for (int m = 0; m < 4; ++m)
                            mma16816(acc[m][np * 2 + hf], aL[m], &bH[np][hf * 2]);
            }
            __syncthreads();
        }
        // epilogue: gate-scaled atomic combine (2 adds per output elem total)
#pragma unroll
        for (int m = 0; m < 4; ++m)
#pragma unroll
            for (int hf = 0; hf < 2; ++hf) {
                const int rl = mt * 128 + wm * 64 + m * 16 + (lane >> 2) + hf * 8;
                if (rl < cnt) {
                    const int   tok = g_pair_tok[off + rl];
                    const float gt  = g_pair_gate[off + rl];
                    float* dst = out + (size_t)tok * DMODEL + n0 + wn * 32 + (lane & 3) * 2;
#pragma unroll
                    for (int n = 0; n < 4; ++n) {
                        atomicAdd(dst + n * 8 + 0, gt * acc[m][n][hf * 2]);
                        atomicAdd(dst + n * 8 + 1, gt * acc[m][n][hf * 2 + 1]);
                    }
                }
            }
        __syncthreads();
    }
}

// ---------------- launch ----------------
extern "C" void kernel_launch(void* const* d_in, const int* in_sizes, int n_in,
                              void* d_out, int out_size) {
    const float* x  = (const float*)d_in[0];
    const float* w1 = (const float*)d_in[1];
    const float* v1 = (const float*)d_in[2];
    const float* w2 = (const float*)d_in[3];
    const float* rw = (const float*)d_in[4];
    float* out = (float*)d_out;

    cudaFuncSetAttribute(gemm1_kernel, cudaFuncAttributeMaxDynamicSharedMemorySize, 2 * STG_SZ);
    cudaFuncSetAttribute(gemm2_kernel, cudaFuncAttributeMaxDynamicSharedMemorySize, 2 * STG_SZ);

    const int nx4 = T_TOK * DMODEL / 4;
    const int nw4 = NEXP * FFN * DMODEL / 4;

    // launch order chosen so gemm1 is the 6th launch (ncu -s 5 -c 1)
    router_kernel<<<T_TOK, 256>>>(x, rw, out);                               // 1
    scatter_kernel<<<1, 256>>>();                                            // 2
    split_x_kernel<<<(nx4 + 255) / 256, 256>>>(x, nx4);                      // 3
    split_w_kernel<<<dim3((nw4 + 255) / 256, 2), 256>>>(w1, v1, nw4);        // 4
    split_w2t_kernel<<<dim3(FFN / 32, DMODEL / 32, NEXP), dim3(32, 8)>>>(w2);// 5
    gemm1_kernel<<<dim3(32, NEXP, 4), 256, 2 * STG_SZ>>>();                  // 6 <- profiled
    const int nh4 = NPAIR * FFN / 4;
    h_split_kernel<<<(nh4 + 255) / 256, 256>>>(nh4);                         // 7
    gemm2_kernel<<<dim3(DMODEL / 128, NEXP, 8), 256, 2 * STG_SZ>>>(out);     // 8
}

// round 8
// speedup vs baseline: 1.5609x; 1.2020x over previous
#include <cuda_runtime.h>
#include <cuda_fp16.h>

#define T_TOK 4096
#define DMODEL 1024
#define NEXP 8
#define FFN 2048
#define TOPK 2
#define NPAIR (T_TOK * TOPK)

// ---------------- device scratch ----------------
__device__ int   g_cnt[NEXP];        // zero at module load; scatter re-zeros at end
__device__ int   g_off[NEXP + 1];
__device__ int   g_fill[NEXP];
__device__ int   g_pair_tok[NPAIR];
__device__ float g_pair_gate[NPAIR];
__device__ int   g_top_e[NPAIR];
__device__ float g_top_w[NPAIR];

__device__ __align__(16) __half g_xs_hi[(size_t)T_TOK * DMODEL];
__device__ __align__(16) __half g_xs_lo[(size_t)T_TOK * DMODEL];
__device__ __align__(16) __half g_w1_hi[(size_t)NEXP * FFN * DMODEL];
__device__ __align__(16) __half g_v1_hi[(size_t)NEXP * FFN * DMODEL];
__device__ __align__(16) __half g_w2t_hi[(size_t)NEXP * DMODEL * FFN];
__device__ __align__(16) float  g_g[(size_t)NPAIR * FFN];
__device__ __align__(16) float  g_l[(size_t)NPAIR * FFN];
__device__ __align__(16) __half g_h_hi[(size_t)NPAIR * FFN];

// ---------------- helpers ----------------
__device__ __forceinline__ unsigned smem_u32(const void* p) {
    unsigned a;
    asm("{ .reg .u64 t; cvta.to.shared.u64 t, %1; cvt.u32.u64 %0, t; }"
        : "=r"(a) : "l"(p));
    return a;
}
// swizzled byte offset in a [rows][32 f16] tile (64B rows); c must be < 64
__device__ __forceinline__ unsigned swz(int row, int c) {
    return (unsigned)(row * 64 + (c ^ ((row & 6) << 3)));
}
__device__ __forceinline__ void ldm4(unsigned* r, unsigned addr) {
    asm volatile("ldmatrix.sync.aligned.m8n8.x4.shared.b16 {%0,%1,%2,%3}, [%4];"
                 : "=r"(r[0]), "=r"(r[1]), "=r"(r[2]), "=r"(r[3]) : "r"(addr));
}
__device__ __forceinline__ void mma16816(float* c, const unsigned* a, const unsigned* b) {
    asm volatile(
        "mma.sync.aligned.m16n8k16.row.col.f32.f16.f16.f32 "
        "{%0,%1,%2,%3}, {%4,%5,%6,%7}, {%8,%9}, {%0,%1,%2,%3};"
        : "+f"(c[0]), "+f"(c[1]), "+f"(c[2]), "+f"(c[3])
        : "r"(a[0]), "r"(a[1]), "r"(a[2]), "r"(a[3]), "r"(b[0]), "r"(b[1]));
}
__device__ __forceinline__ unsigned packh(__half a, __half b) {
    __half2 t = __halves2half2(a, b);
    return *reinterpret_cast<unsigned*>(&t);
}
__device__ __forceinline__ void split2h(float a, float b, unsigned& hi, unsigned& lo) {
    __half ha = __float2half_rn(a), hb = __float2half_rn(b);
    __half la = __float2half_rn(a - __half2float(ha));
    __half lb = __float2half_rn(b - __half2float(hb));
    hi = packh(ha, hb);
    lo = packh(la, lb);
}

// ---------------- router (also zeroes out) ----------------
__global__ void router_kernel(const float* __restrict__ x, const float* __restrict__ rw,
                              float* __restrict__ out) {
    const int t   = blockIdx.x;
    const int tid = threadIdx.x;
    reinterpret_cast<float4*>(out + (size_t)t * DMODEL)[tid] = make_float4(0.f, 0.f, 0.f, 0.f);

    const float4 xr = reinterpret_cast<const float4*>(x + (size_t)t * DMODEL)[tid];
    float part[NEXP];
#pragma unroll
    for (int e = 0; e < NEXP; ++e) {
        const float4 w = reinterpret_cast<const float4*>(rw + (size_t)e * DMODEL)[tid];
        part[e] = xr.x * w.x + xr.y * w.y + xr.z * w.z + xr.w * w.w;
    }
#pragma unroll
    for (int e = 0; e < NEXP; ++e)
#pragma unroll
        for (int o = 16; o > 0; o >>= 1)
            part[e] += __shfl_down_sync(0xffffffffu, part[e], o);
    __shared__ float sm[NEXP][8];
    const int warp = tid >> 5, lane = tid & 31;
    if (lane == 0)
#pragma unroll
        for (int e = 0; e < NEXP; ++e) sm[e][warp] = part[e];
    __syncthreads();
    if (tid == 0) {
        float lg[NEXP]; float mx = -1e30f;
#pragma unroll
        for (int e = 0; e < NEXP; ++e) {
            float s = 0.f;
#pragma unroll
            for (int w = 0; w < 8; ++w) s += sm[e][w];
            lg[e] = s; mx = fmaxf(mx, s);
        }
        float den = 0.f;
#pragma unroll
        for (int e = 0; e < NEXP; ++e) { lg[e] = expf(lg[e] - mx); den += lg[e]; }
#pragma unroll
        for (int e = 0; e < NEXP; ++e) lg[e] /= den;
        int e0 = 0; float v0 = lg[0];
#pragma unroll
        for (int e = 1; e < NEXP; ++e) if (lg[e] > v0) { v0 = lg[e]; e0 = e; }
        int e1 = -1; float v1 = -1.f;
#pragma unroll
        for (int e = 0; e < NEXP; ++e)
            if (e != e0 && lg[e] > v1) { v1 = lg[e]; e1 = e; }
        const float nrm = v0 + v1;
        g_top_e[t * 2 + 0] = e0; g_top_w[t * 2 + 0] = v0 / nrm;
        g_top_e[t * 2 + 1] = e1; g_top_w[t * 2 + 1] = v1 / nrm;
        atomicAdd(&g_cnt[e0], 1);
        atomicAdd(&g_cnt[e1], 1);
    }
}

// ---- scatter (single block): offsets + pair lists + counter reset for replay ----
__global__ void scatter_kernel() {
    if (threadIdx.x == 0) {
        int r = 0;
        g_off[0] = 0;
        for (int e = 0; e < NEXP; ++e) { r += g_cnt[e]; g_off[e + 1] = r; }
    }
    __syncthreads();
    for (int t = threadIdx.x; t < T_TOK; t += blockDim.x) {
#pragma unroll
        for (int k = 0; k < TOPK; ++k) {
            int e = g_top_e[t * TOPK + k];
            int pos = g_off[e] + atomicAdd(&g_fill[e], 1);
            g_pair_tok[pos]  = t;
            g_pair_gate[pos] = g_top_w[t * TOPK + k];
        }
    }
    __syncthreads();
    if (threadIdx.x < NEXP) { g_cnt[threadIdx.x] = 0; g_fill[threadIdx.x] = 0; }
}

// ---------------- x split: fp32 -> fp16 hi/lo ----------------
__global__ void split_x_kernel(const float* __restrict__ s, int n4) {
    int i = blockIdx.x * blockDim.x + threadIdx.x;
    if (i >= n4) return;
    float4 v = reinterpret_cast<const float4*>(s)[i];
    unsigned h0, l0, h1, l1;
    split2h(v.x, v.y, h0, l0);
    split2h(v.z, v.w, h1, l1);
    reinterpret_cast<uint2*>(g_xs_hi)[i] = make_uint2(h0, h1);
    reinterpret_cast<uint2*>(g_xs_lo)[i] = make_uint2(l0, l1);
}

// ---------------- w1+v1 convert: fp32 -> fp16 (hi only), one launch ----------------
__global__ void split_w_kernel(const float* __restrict__ w1, const float* __restrict__ v1,
                               int n4) {
    int i = blockIdx.x * blockDim.x + threadIdx.x;
    if (i >= n4) return;
    const float* s = blockIdx.y ? v1 : w1;
    __half* d = blockIdx.y ? g_v1_hi : g_w1_hi;
    float4 v = reinterpret_cast<const float4*>(s)[i];
    unsigned p0 = packh(__float2half_rn(v.x), __float2half_rn(v.y));
    unsigned p1 = packh(__float2half_rn(v.z), __float2half_rn(v.w));
    reinterpret_cast<uint2*>(d)[i] = make_uint2(p0, p1);
}

// ---------------- w2 transpose + fp16 convert: w2t[e][d][f] ----------------
__global__ void split_w2t_kernel(const float* __restrict__ w2) {
    __shared__ float t[32][33];
    const int e = blockIdx.z;
    const int f0 = blockIdx.x * 32, d0 = blockIdx.y * 32;
    const int tx = threadIdx.x, ty = threadIdx.y;   // 32 x 8
#pragma unroll
    for (int j = 0; j < 4; ++j)
        t[ty + j * 8][tx] = w2[((size_t)e * FFN + f0 + ty + j * 8) * DMODEL + d0 + tx];
    __syncthreads();
#pragma unroll
    for (int j = 0; j < 4; ++j) {
        const int dl = ty + j * 8;
        g_w2t_hi[((size_t)e * DMODEL + d0 + dl) * FFN + f0 + tx] =
            __float2half_rn(t[tx][dl]);
    }
}

// ---------------- SwiGLU -> fp16 h (hi only) ----------------
__global__ void h_split_kernel(int n4) {
    int i = blockIdx.x * blockDim.x + threadIdx.x;
    if (i >= n4) return;
    float4 g = reinterpret_cast<const float4*>(g_g)[i];
    float4 l = reinterpret_cast<const float4*>(g_l)[i];
    float4 h;
    h.x = g.x / (1.f + __expf(-g.x)) * l.x;
    h.y = g.y / (1.f + __expf(-g.y)) * l.y;
    h.z = g.z / (1.f + __expf(-g.z)) * l.z;
    h.w = g.w / (1.f + __expf(-g.w)) * l.w;
    unsigned p0 = packh(__float2half_rn(h.x), __float2half_rn(h.y));
    unsigned p1 = packh(__float2half_rn(h.z), __float2half_rn(h.w));
    reinterpret_cast<uint2*>(g_h_hi)[i] = make_uint2(p0, p1);
}

// ---------------- GEMM1 tile constants (A hi/lo + B hi) ----------------
#define G1_STG 24576
#define G1_AH 0
#define G1_AL 8192
#define G1_BH 16384

// ---------------- GEMM1: g/l = x @ {w1,v1}^T, pair-chunk mainloop (k64) ---------
__global__ void __launch_bounds__(256, 1) gemm1_kernel() {
    extern __shared__ char smem[];
    __shared__ int toks[128];
    const unsigned sb = smem_u32(smem);
    const int tid = threadIdx.x, lane = tid & 31, wid = tid >> 5;
    const int bx = blockIdx.x;
    const int sel = bx >> 4;
    const int n0 = (bx & 15) * 128;
    const int e = blockIdx.y;
    const int off = g_off[e], cnt = g_off[e + 1] - off;
    const __half* __restrict__ Bh = sel ? g_v1_hi : g_w1_hi;
    float* __restrict__ outp = sel ? g_l : g_g;

    const int wm = wid & 1, wn = wid >> 1;
    unsigned aoffs[2][4], boffs[2][2];
#pragma unroll
    for (int ks = 0; ks < 2; ++ks) {
#pragma unroll
        for (int m = 0; m < 4; ++m) {
            int r = wm * 64 + m * 16 + ((lane >> 3) & 1) * 8 + (lane & 7);
            aoffs[ks][m] = swz(r, ((lane >> 4) << 4) + ks * 32);
        }
#pragma unroll
        for (int np = 0; np < 2; ++np) {
            int r = wn * 32 + np * 16 + ((lane >> 4) << 3) + (lane & 7);
            boffs[ks][np] = swz(r, (((lane >> 3) & 1) << 4) + ks * 32);
        }
    }
    const int prow0 = tid >> 2;
    const int pc16 = (tid & 3) * 16;  // byte col
    const int pc8  = (tid & 3) * 8;   // element col
    unsigned soffs[2];
    soffs[0] = swz(prow0, pc16);
    soffs[1] = swz(prow0 + 64, pc16);

    for (int mt = blockIdx.z; mt * 128 < cnt; mt += gridDim.z) {
        if (tid < 128) {
            int r = mt * 128 + tid;
            toks[tid] = (r < cnt) ? g_pair_tok[off + r] : -1;
        }
        __syncthreads();
        float acc[4][4][4];
#pragma unroll
        for (int m = 0; m < 4; ++m)
#pragma unroll
            for (int n = 0; n < 4; ++n)
#pragma unroll
                for (int q = 0; q < 4; ++q) acc[m][n][q] = 0.f;

        uint4 rAh[2][2], rAl[2][2], rBh[2][2];
        const uint4 z4 = make_uint4(0, 0, 0, 0);
        // load one k64 pair (2 chunks of k32) into regs
#define G1_LDG(P)                                                                   \
        {                                                                           \
            _Pragma("unroll")                                                       \
            for (int q = 0; q < 2; ++q) {                                           \
                const int K0 = (P) * 64 + q * 32;                                   \
                _Pragma("unroll")                                                   \
                for (int j = 0; j < 2; ++j) {                                       \
                    const int row = prow0 + j * 64;                                 \
                    const int tok = toks[row];                                      \
                    if (tok >= 0) {                                                 \
                        size_t ao = (size_t)tok * DMODEL + K0 + pc8;                \
                        rAh[q][j] = *reinterpret_cast<const uint4*>(g_xs_hi + ao);  \
                        rAl[q][j] = *reinterpret_cast<const uint4*>(g_xs_lo + ao);  \
                    } else { rAh[q][j] = z4; rAl[q][j] = z4; }                      \
                    size_t bo = ((size_t)e * FFN + n0 + row) * DMODEL + K0 + pc8;   \
                    rBh[q][j] = *reinterpret_cast<const uint4*>(Bh + bo);           \
                }                                                                   \
            }                                                                       \
        }
        G1_LDG(0)
        for (int p = 0; p < DMODEL / 64; ++p) {
            const unsigned sbase = (unsigned)(p & 1) * (2 * G1_STG);
#pragma unroll
            for (int q = 0; q < 2; ++q) {
                const unsigned so = sbase + q * G1_STG;
#pragma unroll
                for (int j = 0; j < 2; ++j) {
                    *reinterpret_cast<uint4*>(smem + so + G1_AH + soffs[j]) = rAh[q][j];
                    *reinterpret_cast<uint4*>(smem + so + G1_AL + soffs[j]) = rAl[q][j];
                    *reinterpret_cast<uint4*>(smem + so + G1_BH + soffs[j]) = rBh[q][j];
                }
            }
            if (p + 1 < DMODEL / 64) G1_LDG(p + 1)
            __syncthreads();
#pragma unroll
            for (int q = 0; q < 2; ++q) {
                const unsigned so = sbase + q * G1_STG;
#pragma unroll
                for (int ks = 0; ks < 2; ++ks) {
                    unsigned aH[4][4], aL[4][4], bH[2][4];
#pragma unroll
                    for (int m = 0; m < 4; ++m) {
                        ldm4(aH[m], sb + so + G1_AH + aoffs[ks][m]);
                        ldm4(aL[m], sb + so + G1_AL + aoffs[ks][m]);
                    }
#pragma unroll
                    for (int np = 0; np < 2; ++np)
                        ldm4(bH[np], sb + so + G1_BH + boffs[ks][np]);
#pragma unroll
                    for (int np = 0; np < 2; ++np)
#pragma unroll
                        for (int hf = 0; hf < 2; ++hf)
#pragma unroll
                            for (int m = 0; m < 4; ++m)
                                mma16816(acc[m][np * 2 + hf], aH[m], &bH[np][hf * 2]);
#pragma unroll
                    for (int np = 0; np < 2; ++np)
#pragma unroll
                        for (int hf = 0; hf < 2; ++hf)
#pragma unroll
                            for (int m = 0; m < 4; ++m)
                                mma16816(acc[m][np * 2 + hf], aL[m], &bH[np][hf * 2]);
                }
            }
            __syncthreads();
        }
        // epilogue: write g or l (fp32)
#pragma unroll
        for (int m = 0; m < 4; ++m)
#pragma unroll
            for (int hf = 0; hf < 2; ++hf) {
                const int rl = mt * 128 + wm * 64 + m * 16 + (lane >> 2) + hf * 8;
                if (rl < cnt) {
                    float* dst = outp + (size_t)(off + rl) * FFN + n0 + wn * 32 + (lane & 3) * 2;
#pragma unroll
                    for (int n = 0; n < 4; ++n) {
                        float2 v = make_float2(acc[m][n][hf * 2], acc[m][n][hf * 2 + 1]);
                        *reinterpret_cast<float2*>(dst + n * 8) = v;
                    }
                }
            }
        __syncthreads();
    }
}

// ---------------- GEMM2 tile constants (A hi only + B hi) ----------------
#define G2_STG 16384
#define G2_AH 0
#define G2_BH 8192

// ---------------- GEMM2: out += gate * (h @ w2t^T), pair-chunk, 1-term ----------
__global__ void __launch_bounds__(256) gemm2_kernel(float* __restrict__ out) {
    extern __shared__ char smem[];
    const unsigned sb = smem_u32(smem);
    const int tid = threadIdx.x, lane = tid & 31, wid = tid >> 5;
    const int n0 = blockIdx.x * 128;
    const int e = blockIdx.y;
    const int off = g_off[e], cnt = g_off[e + 1] - off;

    const int wm = wid & 1, wn = wid >> 1;
    unsigned aoffs[2][4], boffs[2][2];
#pragma unroll
    for (int ks = 0; ks < 2; ++ks) {
#pragma unroll
        for (int m = 0; m < 4; ++m) {
            int r = wm * 64 + m * 16 + ((lane >> 3) & 1) * 8 + (lane & 7);
            aoffs[ks][m] = swz(r, ((lane >> 4) << 4) + ks * 32);
        }
#pragma unroll
        for (int np = 0; np < 2; ++np) {
            int r = wn * 32 + np * 16 + ((lane >> 4) << 3) + (lane & 7);
            boffs[ks][np] = swz(r, (((lane >> 3) & 1) << 4) + ks * 32);
        }
    }
    const int prow0 = tid >> 2;
    const int pc16 = (tid & 3) * 16;
    const int pc8  = (tid & 3) * 8;
    unsigned soffs[2];
    soffs[0] = swz(prow0, pc16);
    soffs[1] = swz(prow0 + 64, pc16);

    for (int mt = blockIdx.z; mt * 128 < cnt; mt += gridDim.z) {
        float acc[4][4][4];
#pragma unroll
        for (int m = 0; m < 4; ++m)
#pragma unroll
            for (int n = 0; n < 4; ++n)
#pragma unroll
                for (int q = 0; q < 4; ++q) acc[m][n][q] = 0.f;

        uint4 rAh[2][2], rBh[2][2];
        const uint4 z4 = make_uint4(0, 0, 0, 0);
#define G2_LDG(P)                                                                   \
        {                                                                           \
            _Pragma("unroll")                                                       \
            for (int q = 0; q < 2; ++q) {                                           \
                const int K0 = (P) * 64 + q * 32;                                   \
                _Pragma("unroll")                                                   \
                for (int j = 0; j < 2; ++j) {                                       \
                    const int row = prow0 + j * 64;                                 \
                    const int rl = mt * 128 + row;                                  \
                    if (rl < cnt) {                                                 \
                        size_t ao = (size_t)(off + rl) * FFN + K0 + pc8;            \
                        rAh[q][j] = *reinterpret_cast<const uint4*>(g_h_hi + ao);   \
                    } else { rAh[q][j] = z4; }                                      \
                    size_t bo = ((size_t)e * DMODEL + n0 + row) * FFN + K0 + pc8;   \
                    rBh[q][j] = *reinterpret_cast<const uint4*>(g_w2t_hi + bo);     \
                }                                                                   \
            }                                                                       \
        }
        G2_LDG(0)
        for (int p = 0; p < FFN / 64; ++p) {
            const unsigned sbase = (unsigned)(p & 1) * (2 * G2_STG);
#pragma unroll
            for (int q = 0; q < 2; ++q) {
                const unsigned so = sbase + q * G2_STG;
#pragma unroll
                for (int j = 0; j < 2; ++j) {
                    *reinterpret_cast<uint4*>(smem + so + G2_AH + soffs[j]) = rAh[q][j];
                    *reinterpret_cast<uint4*>(smem + so + G2_BH + soffs[j]) = rBh[q][j];
                }
            }
            if (p + 1 < FFN / 64) G2_LDG(p + 1)
            __syncthreads();
#pragma unroll
            for (int q = 0; q < 2; ++q) {
                const unsigned so = sbase + q * G2_STG;
#pragma unroll
                for (int ks = 0; ks < 2; ++ks) {
                    unsigned aH[4][4], bH[2][4];
#pragma unroll
                    for (int m = 0; m < 4; ++m)
                        ldm4(aH[m], sb + so + G2_AH + aoffs[ks][m]);
#pragma unroll
                    for (int np = 0; np < 2; ++np)
                        ldm4(bH[np], sb + so + G2_BH + boffs[ks][np]);
#pragma unroll
                    for (int np = 0; np < 2; ++np)
#pragma unroll
                        for (int hf = 0; hf < 2; ++hf)
#pragma unroll
                            for (int m = 0; m < 4; ++m)
                                mma16816(acc[m][np * 2 + hf], aH[m], &bH[np][hf * 2]);
                }
            }
            __syncthreads();
        }
        // epilogue: gate-scaled atomic combine (2 adds per output elem total)
#pragma unroll
        for (int m = 0; m < 4; ++m)
#pragma unroll
            for (int hf = 0; hf < 2; ++hf) {
                const int rl = mt * 128 + wm * 64 + m * 16 + (lane >> 2) + hf * 8;
                if (rl < cnt) {
                    const int   tok = g_pair_tok[off + rl];
                    const float gt  = g_pair_gate[off + rl];
                    float* dst = out + (size_t)tok * DMODEL + n0 + wn * 32 + (lane & 3) * 2;
#pragma unroll
                    for (int n = 0; n < 4; ++n) {
                        atomicAdd(dst + n * 8 + 0, gt * acc[m][n][hf * 2]);
                        atomicAdd(dst + n * 8 + 1, gt * acc[m][n][hf * 2 + 1]);
                    }
                }
            }
        __syncthreads();
    }
}

// ---------------- launch ----------------
extern "C" void kernel_launch(void* const* d_in, const int* in_sizes, int n_in,
                              void* d_out, int out_size) {
    const float* x  = (const float*)d_in[0];
    const float* w1 = (const float*)d_in[1];
    const float* v1 = (const float*)d_in[2];
    const float* w2 = (const float*)d_in[3];
    const float* rw = (const float*)d_in[4];
    float* out = (float*)d_out;

    cudaFuncSetAttribute(gemm1_kernel, cudaFuncAttributeMaxDynamicSharedMemorySize, 4 * G1_STG);
    cudaFuncSetAttribute(gemm2_kernel, cudaFuncAttributeMaxDynamicSharedMemorySize, 4 * G2_STG);

    const int nx4 = T_TOK * DMODEL / 4;
    const int nw4 = NEXP * FFN * DMODEL / 4;

    router_kernel<<<T_TOK, 256>>>(x, rw, out);
    scatter_kernel<<<1, 256>>>();
    split_x_kernel<<<(nx4 + 255) / 256, 256>>>(x, nx4);
    split_w_kernel<<<dim3((nw4 + 255) / 256, 2), 256>>>(w1, v1, nw4);
    split_w2t_kernel<<<dim3(FFN / 32, DMODEL / 32, NEXP), dim3(32, 8)>>>(w2);
    gemm1_kernel<<<dim3(32, NEXP, 4), 256, 4 * G1_STG>>>();
    const int nh4 = NPAIR * FFN / 4;
    h_split_kernel<<<(nh4 + 255) / 256, 256>>>(nh4);
    gemm2_kernel<<<dim3(DMODEL / 128, NEXP, 8), 256, 4 * G2_STG>>>(out);
}

// round 9
// speedup vs baseline: 2.0538x; 1.3158x over previous
#include <cuda_runtime.h>
#include <cuda_fp16.h>

#define T_TOK 4096
#define DMODEL 1024
#define NEXP 8
#define FFN 2048
#define TOPK 2
#define NPAIR (T_TOK * TOPK)

// ---------------- device scratch ----------------
__device__ int   g_cnt[NEXP];        // zero at module load; scatter re-zeros at end
__device__ int   g_off[NEXP + 1];
__device__ int   g_fill[NEXP];
__device__ int   g_pair_tok[NPAIR];
__device__ float g_pair_gate[NPAIR];
__device__ int   g_top_e[NPAIR];
__device__ float g_top_w[NPAIR];

__device__ __align__(16) __half g_xs_hi[(size_t)T_TOK * DMODEL];
__device__ __align__(16) __half g_w1_hi[(size_t)NEXP * FFN * DMODEL];
__device__ __align__(16) __half g_v1_hi[(size_t)NEXP * FFN * DMODEL];
__device__ __align__(16) __half g_w2t_hi[(size_t)NEXP * DMODEL * FFN];
__device__ __align__(16) float  g_g[(size_t)NPAIR * FFN];
__device__ __align__(16) float  g_l[(size_t)NPAIR * FFN];
__device__ __align__(16) __half g_h_hi[(size_t)NPAIR * FFN];

// ---------------- helpers ----------------
__device__ __forceinline__ unsigned smem_u32(const void* p) {
    unsigned a;
    asm("{ .reg .u64 t; cvta.to.shared.u64 t, %1; cvt.u32.u64 %0, t; }"
        : "=r"(a) : "l"(p));
    return a;
}
// swizzled byte offset in a [rows][32 f16] tile (64B rows); c must be < 64
__device__ __forceinline__ unsigned swz(int row, int c) {
    return (unsigned)(row * 64 + (c ^ ((row & 6) << 3)));
}
__device__ __forceinline__ void ldm4(unsigned* r, unsigned addr) {
    asm volatile("ldmatrix.sync.aligned.m8n8.x4.shared.b16 {%0,%1,%2,%3}, [%4];"
                 : "=r"(r[0]), "=r"(r[1]), "=r"(r[2]), "=r"(r[3]) : "r"(addr));
}
__device__ __forceinline__ void mma16816(float* c, const unsigned* a, const unsigned* b) {
    asm volatile(
        "mma.sync.aligned.m16n8k16.row.col.f32.f16.f16.f32 "
        "{%0,%1,%2,%3}, {%4,%5,%6,%7}, {%8,%9}, {%0,%1,%2,%3};"
        : "+f"(c[0]), "+f"(c[1]), "+f"(c[2]), "+f"(c[3])
        : "r"(a[0]), "r"(a[1]), "r"(a[2]), "r"(a[3]), "r"(b[0]), "r"(b[1]));
}
__device__ __forceinline__ unsigned packh(__half a, __half b) {
    __half2 t = __halves2half2(a, b);
    return *reinterpret_cast<unsigned*>(&t);
}

// ---------------- router (also zeroes out) ----------------
__global__ void router_kernel(const float* __restrict__ x, const float* __restrict__ rw,
                              float* __restrict__ out) {
    const int t   = blockIdx.x;
    const int tid = threadIdx.x;
    reinterpret_cast<float4*>(out + (size_t)t * DMODEL)[tid] = make_float4(0.f, 0.f, 0.f, 0.f);

    const float4 xr = reinterpret_cast<const float4*>(x + (size_t)t * DMODEL)[tid];
    float part[NEXP];
#pragma unroll
    for (int e = 0; e < NEXP; ++e) {
        const float4 w = reinterpret_cast<const float4*>(rw + (size_t)e * DMODEL)[tid];
        part[e] = xr.x * w.x + xr.y * w.y + xr.z * w.z + xr.w * w.w;
    }
#pragma unroll
    for (int e = 0; e < NEXP; ++e)
#pragma unroll
        for (int o = 16; o > 0; o >>= 1)
            part[e] += __shfl_down_sync(0xffffffffu, part[e], o);
    __shared__ float sm[NEXP][8];
    const int warp = tid >> 5, lane = tid & 31;
    if (lane == 0)
#pragma unroll
        for (int e = 0; e < NEXP; ++e) sm[e][warp] = part[e];
    __syncthreads();
    if (tid == 0) {
        float lg[NEXP]; float mx = -1e30f;
#pragma unroll
        for (int e = 0; e < NEXP; ++e) {
            float s = 0.f;
#pragma unroll
            for (int w = 0; w < 8; ++w) s += sm[e][w];
            lg[e] = s; mx = fmaxf(mx, s);
        }
        float den = 0.f;
#pragma unroll
        for (int e = 0; e < NEXP; ++e) { lg[e] = expf(lg[e] - mx); den += lg[e]; }
#pragma unroll
        for (int e = 0; e < NEXP; ++e) lg[e] /= den;
        int e0 = 0; float v0 = lg[0];
#pragma unroll
        for (int e = 1; e < NEXP; ++e) if (lg[e] > v0) { v0 = lg[e]; e0 = e; }
        int e1 = -1; float v1 = -1.f;
#pragma unroll
        for (int e = 0; e < NEXP; ++e)
            if (e != e0 && lg[e] > v1) { v1 = lg[e]; e1 = e; }
        const float nrm = v0 + v1;
        g_top_e[t * 2 + 0] = e0; g_top_w[t * 2 + 0] = v0 / nrm;
        g_top_e[t * 2 + 1] = e1; g_top_w[t * 2 + 1] = v1 / nrm;
        atomicAdd(&g_cnt[e0], 1);
        atomicAdd(&g_cnt[e1], 1);
    }
}

// ---- scatter (single block): offsets + pair lists + counter reset for replay ----
__global__ void scatter_kernel() {
    if (threadIdx.x == 0) {
        int r = 0;
        g_off[0] = 0;
        for (int e = 0; e < NEXP; ++e) { r += g_cnt[e]; g_off[e + 1] = r; }
    }
    __syncthreads();
    for (int t = threadIdx.x; t < T_TOK; t += blockDim.x) {
#pragma unroll
        for (int k = 0; k < TOPK; ++k) {
            int e = g_top_e[t * TOPK + k];
            int pos = g_off[e] + atomicAdd(&g_fill[e], 1);
            g_pair_tok[pos]  = t;
            g_pair_gate[pos] = g_top_w[t * TOPK + k];
        }
    }
    __syncthreads();
    if (threadIdx.x < NEXP) { g_cnt[threadIdx.x] = 0; g_fill[threadIdx.x] = 0; }
}

// ---------------- x convert: fp32 -> fp16 ----------------
__global__ void split_x_kernel(const float* __restrict__ s, int n4) {
    int i = blockIdx.x * blockDim.x + threadIdx.x;
    if (i >= n4) return;
    float4 v = reinterpret_cast<const float4*>(s)[i];
    unsigned p0 = packh(__float2half_rn(v.x), __float2half_rn(v.y));
    unsigned p1 = packh(__float2half_rn(v.z), __float2half_rn(v.w));
    reinterpret_cast<uint2*>(g_xs_hi)[i] = make_uint2(p0, p1);
}

// ---------------- w1+v1 convert: fp32 -> fp16, one launch ----------------
__global__ void split_w_kernel(const float* __restrict__ w1, const float* __restrict__ v1,
                               int n4) {
    int i = blockIdx.x * blockDim.x + threadIdx.x;
    if (i >= n4) return;
    const float* s = blockIdx.y ? v1 : w1;
    __half* d = blockIdx.y ? g_v1_hi : g_w1_hi;
    float4 v = reinterpret_cast<const float4*>(s)[i];
    unsigned p0 = packh(__float2half_rn(v.x), __float2half_rn(v.y));
    unsigned p1 = packh(__float2half_rn(v.z), __float2half_rn(v.w));
    reinterpret_cast<uint2*>(d)[i] = make_uint2(p0, p1);
}

// ---------------- w2 transpose + fp16 convert: w2t[e][d][f] ----------------
__global__ void split_w2t_kernel(const float* __restrict__ w2) {
    __shared__ float t[32][33];
    const int e = blockIdx.z;
    const int f0 = blockIdx.x * 32, d0 = blockIdx.y * 32;
    const int tx = threadIdx.x, ty = threadIdx.y;   // 32 x 8
#pragma unroll
    for (int j = 0; j < 4; ++j)
        t[ty + j * 8][tx] = w2[((size_t)e * FFN + f0 + ty + j * 8) * DMODEL + d0 + tx];
    __syncthreads();
#pragma unroll
    for (int j = 0; j < 4; ++j) {
        const int dl = ty + j * 8;
        g_w2t_hi[((size_t)e * DMODEL + d0 + dl) * FFN + f0 + tx] =
            __float2half_rn(t[tx][dl]);
    }
}

// ---------------- SwiGLU -> fp16 h ----------------
__global__ void h_split_kernel(int n4) {
    int i = blockIdx.x * blockDim.x + threadIdx.x;
    if (i >= n4) return;
    float4 g = reinterpret_cast<const float4*>(g_g)[i];
    float4 l = reinterpret_cast<const float4*>(g_l)[i];
    float4 h;
    h.x = g.x / (1.f + __expf(-g.x)) * l.x;
    h.y = g.y / (1.f + __expf(-g.y)) * l.y;
    h.z = g.z / (1.f + __expf(-g.z)) * l.z;
    h.w = g.w / (1.f + __expf(-g.w)) * l.w;
    unsigned p0 = packh(__float2half_rn(h.x), __float2half_rn(h.y));
    unsigned p1 = packh(__float2half_rn(h.z), __float2half_rn(h.w));
    reinterpret_cast<uint2*>(g_h_hi)[i] = make_uint2(p0, p1);
}

// ---------------- GEMM1 tile constants (A hi + B hi, single-term) ----------------
#define G1_STG 16384
#define G1_AH 0
#define G1_BH 8192

// ---------------- GEMM1: g/l = x @ {w1,v1}^T, pair-chunk mainloop (k64) ---------
__global__ void __launch_bounds__(256) gemm1_kernel() {
    extern __shared__ char smem[];
    __shared__ int toks[128];
    const unsigned sb = smem_u32(smem);
    const int tid = threadIdx.x, lane = tid & 31, wid = tid >> 5;
    const int bx = blockIdx.x;
    const int sel = bx >> 4;
    const int n0 = (bx & 15) * 128;
    const int e = blockIdx.y;
    const int off = g_off[e], cnt = g_off[e + 1] - off;
    const __half* __restrict__ Bh = sel ? g_v1_hi : g_w1_hi;
    float* __restrict__ outp = sel ? g_l : g_g;

    const int wm = wid & 1, wn = wid >> 1;
    unsigned aoffs[2][4], boffs[2][2];
#pragma unroll
    for (int ks = 0; ks < 2; ++ks) {
#pragma unroll
        for (int m = 0; m < 4; ++m) {
            int r = wm * 64 + m * 16 + ((lane >> 3) & 1) * 8 + (lane & 7);
            aoffs[ks][m] = swz(r, ((lane >> 4) << 4) + ks * 32);
        }
#pragma unroll
        for (int np = 0; np < 2; ++np) {
            int r = wn * 32 + np * 16 + ((lane >> 4) << 3) + (lane & 7);
            boffs[ks][np] = swz(r, (((lane >> 3) & 1) << 4) + ks * 32);
        }
    }
    const int prow0 = tid >> 2;
    const int pc16 = (tid & 3) * 16;  // byte col
    const int pc8  = (tid & 3) * 8;   // element col
    unsigned soffs[2];
    soffs[0] = swz(prow0, pc16);
    soffs[1] = swz(prow0 + 64, pc16);

    for (int mt = blockIdx.z; mt * 128 < cnt; mt += gridDim.z) {
        if (tid < 128) {
            int r = mt * 128 + tid;
            toks[tid] = (r < cnt) ? g_pair_tok[off + r] : -1;
        }
        __syncthreads();
        float acc[4][4][4];
#pragma unroll
        for (int m = 0; m < 4; ++m)
#pragma unroll
            for (int n = 0; n < 4; ++n)
#pragma unroll
                for (int q = 0; q < 4; ++q) acc[m][n][q] = 0.f;

        uint4 rAh[2][2], rBh[2][2];
        const uint4 z4 = make_uint4(0, 0, 0, 0);
        // load one k64 pair (2 chunks of k32) into regs
#define G1_LDG(P)                                                                   \
        {                                                                           \
            _Pragma("unroll")                                                       \
            for (int q = 0; q < 2; ++q) {                                           \
                const int K0 = (P) * 64 + q * 32;                                   \
                _Pragma("unroll")                                                   \
                for (int j = 0; j < 2; ++j) {                                       \
                    const int row = prow0 + j * 64;                                 \
                    const int tok = toks[row];                                      \
                    if (tok >= 0) {                                                 \
                        size_t ao = (size_t)tok * DMODEL + K0 + pc8;                \
                        rAh[q][j] = *reinterpret_cast<const uint4*>(g_xs_hi + ao);  \
                    } else { rAh[q][j] = z4; }                                      \
                    size_t bo = ((size_t)e * FFN + n0 + row) * DMODEL + K0 + pc8;   \
                    rBh[q][j] = *reinterpret_cast<const uint4*>(Bh + bo);           \
                }                                                                   \
            }                                                                       \
        }
        G1_LDG(0)
        for (int p = 0; p < DMODEL / 64; ++p) {
            const unsigned sbase = (unsigned)(p & 1) * (2 * G1_STG);
#pragma unroll
            for (int q = 0; q < 2; ++q) {
                const unsigned so = sbase + q * G1_STG;
#pragma unroll
                for (int j = 0; j < 2; ++j) {
                    *reinterpret_cast<uint4*>(smem + so + G1_AH + soffs[j]) = rAh[q][j];
                    *reinterpret_cast<uint4*>(smem + so + G1_BH + soffs[j]) = rBh[q][j];
                }
            }
            if (p + 1 < DMODEL / 64) G1_LDG(p + 1)
            __syncthreads();
#pragma unroll
            for (int q = 0; q < 2; ++q) {
                const unsigned so = sbase + q * G1_STG;
#pragma unroll
                for (int ks = 0; ks < 2; ++ks) {
                    unsigned aH[4][4], bH[2][4];
#pragma unroll
                    for (int m = 0; m < 4; ++m)
                        ldm4(aH[m], sb + so + G1_AH + aoffs[ks][m]);
#pragma unroll
                    for (int np = 0; np < 2; ++np)
                        ldm4(bH[np], sb + so + G1_BH + boffs[ks][np]);
#pragma unroll
                    for (int np = 0; np < 2; ++np)
#pragma unroll
                        for (int hf = 0; hf < 2; ++hf)
#pragma unroll
                            for (int m = 0; m < 4; ++m)
                                mma16816(acc[m][np * 2 + hf], aH[m], &bH[np][hf * 2]);
                }
            }
            __syncthreads();
        }
        // epilogue: write g or l (fp32)
#pragma unroll
        for (int m = 0; m < 4; ++m)
#pragma unroll
            for (int hf = 0; hf < 2; ++hf) {
                const int rl = mt * 128 + wm * 64 + m * 16 + (lane >> 2) + hf * 8;
                if (rl < cnt) {
                    float* dst = outp + (size_t)(off + rl) * FFN + n0 + wn * 32 + (lane & 3) * 2;
#pragma unroll
                    for (int n = 0; n < 4; ++n) {
                        float2 v = make_float2(acc[m][n][hf * 2], acc[m][n][hf * 2 + 1]);
                        *reinterpret_cast<float2*>(dst + n * 8) = v;
                    }
                }
            }
        __syncthreads();
    }
}

// ---------------- GEMM2 tile constants (A hi only + B hi) ----------------
#define G2_STG 16384
#define G2_AH 0
#define G2_BH 8192

// ---------------- GEMM2: out += gate * (h @ w2t^T), pair-chunk, 1-term ----------
__global__ void __launch_bounds__(256) gemm2_kernel(float* __restrict__ out) {
    extern __shared__ char smem[];
    const unsigned sb = smem_u32(smem);
    const int tid = threadIdx.x, lane = tid & 31, wid = tid >> 5;
    const int n0 = blockIdx.x * 128;
    const int e = blockIdx.y;
    const int off = g_off[e], cnt = g_off[e + 1] - off;

    const int wm = wid & 1, wn = wid >> 1;
    unsigned aoffs[2][4], boffs[2][2];
#pragma unroll
    for (int ks = 0; ks < 2; ++ks) {
#pragma unroll
        for (int m = 0; m < 4; ++m) {
            int r = wm * 64 + m * 16 + ((lane >> 3) & 1) * 8 + (lane & 7);
            aoffs[ks][m] = swz(r, ((lane >> 4) << 4) + ks * 32);
        }
#pragma unroll
        for (int np = 0; np < 2; ++np) {
            int r = wn * 32 + np * 16 + ((lane >> 4) << 3) + (lane & 7);
            boffs[ks][np] = swz(r, (((lane >> 3) & 1) << 4) + ks * 32);
        }
    }
    const int prow0 = tid >> 2;
    const int pc16 = (tid & 3) * 16;
    const int pc8  = (tid & 3) * 8;
    unsigned soffs[2];
    soffs[0] = swz(prow0, pc16);
    soffs[1] = swz(prow0 + 64, pc16);

    for (int mt = blockIdx.z; mt * 128 < cnt; mt += gridDim.z) {
        float acc[4][4][4];
#pragma unroll
        for (int m = 0; m < 4; ++m)
#pragma unroll
            for (int n = 0; n < 4; ++n)
#pragma unroll
                for (int q = 0; q < 4; ++q) acc[m][n][q] = 0.f;

        uint4 rAh[2][2], rBh[2][2];
        const uint4 z4 = make_uint4(0, 0, 0, 0);
#define G2_LDG(P)                                                                   \
        {                                                                           \
            _Pragma("unroll")                                                       \
            for (int q = 0; q < 2; ++q) {                                           \
                const int K0 = (P) * 64 + q * 32;                                   \
                _Pragma("unroll")                                                   \
                for (int j = 0; j < 2; ++j) {                                       \
                    const int row = prow0 + j * 64;                                 \
                    const int rl = mt * 128 + row;                                  \
                    if (rl < cnt) {                                                 \
                        size_t ao = (size_t)(off + rl) * FFN + K0 + pc8;            \
                        rAh[q][j] = *reinterpret_cast<const uint4*>(g_h_hi + ao);   \
                    } else { rAh[q][j] = z4; }                                      \
                    size_t bo = ((size_t)e * DMODEL + n0 + row) * FFN + K0 + pc8;   \
                    rBh[q][j] = *reinterpret_cast<const uint4*>(g_w2t_hi + bo);     \
                }                                                                   \
            }                                                                       \
        }
        G2_LDG(0)
        for (int p = 0; p < FFN / 64; ++p) {
            const unsigned sbase = (unsigned)(p & 1) * (2 * G2_STG);
#pragma unroll
            for (int q = 0; q < 2; ++q) {
                const unsigned so = sbase + q * G2_STG;
#pragma unroll
                for (int j = 0; j < 2; ++j) {
                    *reinterpret_cast<uint4*>(smem + so + G2_AH + soffs[j]) = rAh[q][j];
                    *reinterpret_cast<uint4*>(smem + so + G2_BH + soffs[j]) = rBh[q][j];
                }
            }
            if (p + 1 < FFN / 64) G2_LDG(p + 1)
            __syncthreads();
#pragma unroll
            for (int q = 0; q < 2; ++q) {
                const unsigned so = sbase + q * G2_STG;
#pragma unroll
                for (int ks = 0; ks < 2; ++ks) {
                    unsigned aH[4][4], bH[2][4];
#pragma unroll
                    for (int m = 0; m < 4; ++m)
                        ldm4(aH[m], sb + so + G2_AH + aoffs[ks][m]);
#pragma unroll
                    for (int np = 0; np < 2; ++np)
                        ldm4(bH[np], sb + so + G2_BH + boffs[ks][np]);
#pragma unroll
                    for (int np = 0; np < 2; ++np)
#pragma unroll
                        for (int hf = 0; hf < 2; ++hf)
#pragma unroll
                            for (int m = 0; m < 4; ++m)
                                mma16816(acc[m][np * 2 + hf], aH[m], &bH[np][hf * 2]);
                }
            }
            __syncthreads();
        }
        // epilogue: gate-scaled atomic combine (2 adds per output elem total)
#pragma unroll
        for (int m = 0; m < 4; ++m)
#pragma unroll
            for (int hf = 0; hf < 2; ++hf) {
                const int rl = mt * 128 + wm * 64 + m * 16 + (lane >> 2) + hf * 8;
                if (rl < cnt) {
                    const int   tok = g_pair_tok[off + rl];
                    const float gt  = g_pair_gate[off + rl];
                    float* dst = out + (size_t)tok * DMODEL + n0 + wn * 32 + (lane & 3) * 2;
#pragma unroll
                    for (int n = 0; n < 4; ++n) {
                        atomicAdd(dst + n * 8 + 0, gt * acc[m][n][hf * 2]);
                        atomicAdd(dst + n * 8 + 1, gt * acc[m][n][hf * 2 + 1]);
                    }
                }
            }
        __syncthreads();
    }
}

// ---------------- launch ----------------
extern "C" void kernel_launch(void* const* d_in, const int* in_sizes, int n_in,
                              void* d_out, int out_size) {
    const float* x  = (const float*)d_in[0];
    const float* w1 = (const float*)d_in[1];
    const float* v1 = (const float*)d_in[2];
    const float* w2 = (const float*)d_in[3];
    const float* rw = (const float*)d_in[4];
    float* out = (float*)d_out;

    cudaFuncSetAttribute(gemm1_kernel, cudaFuncAttributeMaxDynamicSharedMemorySize, 4 * G1_STG);
    cudaFuncSetAttribute(gemm2_kernel, cudaFuncAttributeMaxDynamicSharedMemorySize, 4 * G2_STG);

    const int nx4 = T_TOK * DMODEL / 4;
    const int nw4 = NEXP * FFN * DMODEL / 4;

    router_kernel<<<T_TOK, 256>>>(x, rw, out);
    scatter_kernel<<<1, 256>>>();
    split_x_kernel<<<(nx4 + 255) / 256, 256>>>(x, nx4);
    split_w_kernel<<<dim3((nw4 + 255) / 256, 2), 256>>>(w1, v1, nw4);
    split_w2t_kernel<<<dim3(FFN / 32, DMODEL / 32, NEXP), dim3(32, 8)>>>(w2);
    gemm1_kernel<<<dim3(32, NEXP, 4), 256, 4 * G1_STG>>>();
    const int nh4 = NPAIR * FFN / 4;
    h_split_kernel<<<(nh4 + 255) / 256, 256>>>(nh4);
    gemm2_kernel<<<dim3(DMODEL / 128, NEXP, 8), 256, 4 * G2_STG>>>(out);
}

// round 10
// speedup vs baseline: 2.1002x; 1.0225x over previous
#include <cuda_runtime.h>
#include <cuda_fp16.h>

#define T_TOK 4096
#define DMODEL 1024
#define NEXP 8
#define FFN 2048
#define TOPK 2
#define NPAIR (T_TOK * TOPK)

// ---------------- device scratch ----------------
__device__ int   g_cnt[NEXP];        // zero at module load; scatter re-zeros at end
__device__ int   g_off[NEXP + 1];
__device__ int   g_fill[NEXP];
__device__ int   g_pair_tok[NPAIR];
__device__ float g_pair_gate[NPAIR];
__device__ int   g_top_e[NPAIR];
__device__ float g_top_w[NPAIR];

__device__ __align__(16) __half g_xs_hi[(size_t)T_TOK * DMODEL];
// interleaved first-layer weights: row 2f = w1[f], row 2f+1 = v1[f]
__device__ __align__(16) __half g_wv1[(size_t)NEXP * 2 * FFN * DMODEL];
__device__ __align__(16) __half g_w2t_hi[(size_t)NEXP * DMODEL * FFN];
__device__ __align__(16) __half g_h_hi[(size_t)NPAIR * FFN];

// ---------------- helpers ----------------
__device__ __forceinline__ unsigned smem_u32(const void* p) {
    unsigned a;
    asm("{ .reg .u64 t; cvta.to.shared.u64 t, %1; cvt.u32.u64 %0, t; }"
        : "=r"(a) : "l"(p));
    return a;
}
// swizzled byte offset in a [rows][32 f16] tile (64B rows); c must be < 64
__device__ __forceinline__ unsigned swz(int row, int c) {
    return (unsigned)(row * 64 + (c ^ ((row & 6) << 3)));
}
__device__ __forceinline__ void ldm4(unsigned* r, unsigned addr) {
    asm volatile("ldmatrix.sync.aligned.m8n8.x4.shared.b16 {%0,%1,%2,%3}, [%4];"
                 : "=r"(r[0]), "=r"(r[1]), "=r"(r[2]), "=r"(r[3]) : "r"(addr));
}
__device__ __forceinline__ void mma16816(float* c, const unsigned* a, const unsigned* b) {
    asm volatile(
        "mma.sync.aligned.m16n8k16.row.col.f32.f16.f16.f32 "
        "{%0,%1,%2,%3}, {%4,%5,%6,%7}, {%8,%9}, {%0,%1,%2,%3};"
        : "+f"(c[0]), "+f"(c[1]), "+f"(c[2]), "+f"(c[3])
        : "r"(a[0]), "r"(a[1]), "r"(a[2]), "r"(a[3]), "r"(b[0]), "r"(b[1]));
}
__device__ __forceinline__ unsigned packh(__half a, __half b) {
    __half2 t = __halves2half2(a, b);
    return *reinterpret_cast<unsigned*>(&t);
}

// ---------------- router (also zeroes out) ----------------
__global__ void router_kernel(const float* __restrict__ x, const float* __restrict__ rw,
                              float* __restrict__ out) {
    const int t   = blockIdx.x;
    const int tid = threadIdx.x;
    reinterpret_cast<float4*>(out + (size_t)t * DMODEL)[tid] = make_float4(0.f, 0.f, 0.f, 0.f);

    const float4 xr = reinterpret_cast<const float4*>(x + (size_t)t * DMODEL)[tid];
    float part[NEXP];
#pragma unroll
    for (int e = 0; e < NEXP; ++e) {
        const float4 w = reinterpret_cast<const float4*>(rw + (size_t)e * DMODEL)[tid];
        part[e] = xr.x * w.x + xr.y * w.y + xr.z * w.z + xr.w * w.w;
    }
#pragma unroll
    for (int e = 0; e < NEXP; ++e)
#pragma unroll
        for (int o = 16; o > 0; o >>= 1)
            part[e] += __shfl_down_sync(0xffffffffu, part[e], o);
    __shared__ float sm[NEXP][8];
    const int warp = tid >> 5, lane = tid & 31;
    if (lane == 0)
#pragma unroll
        for (int e = 0; e < NEXP; ++e) sm[e][warp] = part[e];
    __syncthreads();
    if (tid == 0) {
        float lg[NEXP]; float mx = -1e30f;
#pragma unroll
        for (int e = 0; e < NEXP; ++e) {
            float s = 0.f;
#pragma unroll
            for (int w = 0; w < 8; ++w) s += sm[e][w];
            lg[e] = s; mx = fmaxf(mx, s);
        }
        float den = 0.f;
#pragma unroll
        for (int e = 0; e < NEXP; ++e) { lg[e] = expf(lg[e] - mx); den += lg[e]; }
#pragma unroll
        for (int e = 0; e < NEXP; ++e) lg[e] /= den;
        int e0 = 0; float v0 = lg[0];
#pragma unroll
        for (int e = 1; e < NEXP; ++e) if (lg[e] > v0) { v0 = lg[e]; e0 = e; }
        int e1 = -1; float v1 = -1.f;
#pragma unroll
        for (int e = 0; e < NEXP; ++e)
            if (e != e0 && lg[e] > v1) { v1 = lg[e]; e1 = e; }
        const float nrm = v0 + v1;
        g_top_e[t * 2 + 0] = e0; g_top_w[t * 2 + 0] = v0 / nrm;
        g_top_e[t * 2 + 1] = e1; g_top_w[t * 2 + 1] = v1 / nrm;
        atomicAdd(&g_cnt[e0], 1);
        atomicAdd(&g_cnt[e1], 1);
    }
}

// ---- scatter (single block): offsets + pair lists + counter reset for replay ----
__global__ void scatter_kernel() {
    if (threadIdx.x == 0) {
        int r = 0;
        g_off[0] = 0;
        for (int e = 0; e < NEXP; ++e) { r += g_cnt[e]; g_off[e + 1] = r; }
    }
    __syncthreads();
    for (int t = threadIdx.x; t < T_TOK; t += blockDim.x) {
#pragma unroll
        for (int k = 0; k < TOPK; ++k) {
            int e = g_top_e[t * TOPK + k];
            int pos = g_off[e] + atomicAdd(&g_fill[e], 1);
            g_pair_tok[pos]  = t;
            g_pair_gate[pos] = g_top_w[t * TOPK + k];
        }
    }
    __syncthreads();
    if (threadIdx.x < NEXP) { g_cnt[threadIdx.x] = 0; g_fill[threadIdx.x] = 0; }
}

// ---------------- x convert: fp32 -> fp16 ----------------
__global__ void split_x_kernel(const float* __restrict__ s, int n4) {
    int i = blockIdx.x * blockDim.x + threadIdx.x;
    if (i >= n4) return;
    float4 v = reinterpret_cast<const float4*>(s)[i];
    unsigned p0 = packh(__float2half_rn(v.x), __float2half_rn(v.y));
    unsigned p1 = packh(__float2half_rn(v.z), __float2half_rn(v.w));
    reinterpret_cast<uint2*>(g_xs_hi)[i] = make_uint2(p0, p1);
}

// ------- w1+v1 convert fp32 -> fp16, interleaved rows (2f | 2f+1), one launch ----
__global__ void split_wv_kernel(const float* __restrict__ w1, const float* __restrict__ v1,
                                int n4) {
    int i = blockIdx.x * blockDim.x + threadIdx.x;
    if (i >= n4) return;
    const int sel = blockIdx.y;
    const float* s = sel ? v1 : w1;
    float4 v = reinterpret_cast<const float4*>(s)[i];
    unsigned p0 = packh(__float2half_rn(v.x), __float2half_rn(v.y));
    unsigned p1 = packh(__float2half_rn(v.z), __float2half_rn(v.w));
    const int row = i >> 8;               // i / (DMODEL/4)
    const int dc  = i & 255;              // float4 index within row
    const int e = row / FFN, f = row % FFN;
    const size_t drow = (size_t)e * 2 * FFN + 2 * f + sel;
    reinterpret_cast<uint2*>(g_wv1)[drow * 256 + dc] = make_uint2(p0, p1);
}

// ---------------- w2 transpose + fp16 convert: w2t[e][d][f] ----------------
__global__ void split_w2t_kernel(const float* __restrict__ w2) {
    __shared__ float t[32][33];
    const int e = blockIdx.z;
    const int f0 = blockIdx.x * 32, d0 = blockIdx.y * 32;
    const int tx = threadIdx.x, ty = threadIdx.y;   // 32 x 8
#pragma unroll
    for (int j = 0; j < 4; ++j)
        t[ty + j * 8][tx] = w2[((size_t)e * FFN + f0 + ty + j * 8) * DMODEL + d0 + tx];
    __syncthreads();
#pragma unroll
    for (int j = 0; j < 4; ++j) {
        const int dl = ty + j * 8;
        g_w2t_hi[((size_t)e * DMODEL + d0 + dl) * FFN + f0 + tx] =
            __float2half_rn(t[tx][dl]);
    }
}

// ---------------- GEMM1 tile constants ----------------
#define G1_STG 16384
#define G1_AH 0
#define G1_BH 8192
#define HST_STRIDE 72   // halves per row in epilogue staging (bank-shift padding)

// ---- GEMM1 (fused): h = silu(x@w1^T)*(x@v1^T) via interleaved B rows ----------
// Block covers 128 pairs x 64 f-values (B tile = 128 interleaved rows).
// Each thread's acc column pair = (g_f, l_f) -> thread-local SwiGLU epilogue.
__global__ void __launch_bounds__(256) gemm1_kernel() {
    extern __shared__ char smem[];
    __shared__ int toks[128];
    const unsigned sb = smem_u32(smem);
    const int tid = threadIdx.x, lane = tid & 31, wid = tid >> 5;
    const int bx = blockIdx.x;              // f-tile: [bx*64, bx*64+64)
    const int e = blockIdx.y;
    const int off = g_off[e], cnt = g_off[e + 1] - off;

    const int wm = wid & 1, wn = wid >> 1;
    unsigned aoffs[2][4], boffs[2][2];
#pragma unroll
    for (int ks = 0; ks < 2; ++ks) {
#pragma unroll
        for (int m = 0; m < 4; ++m) {
            int r = wm * 64 + m * 16 + ((lane >> 3) & 1) * 8 + (lane & 7);
            aoffs[ks][m] = swz(r, ((lane >> 4) << 4) + ks * 32);
        }
#pragma unroll
        for (int np = 0; np < 2; ++np) {
            int r = wn * 32 + np * 16 + ((lane >> 4) << 3) + (lane & 7);
            boffs[ks][np] = swz(r, (((lane >> 3) & 1) << 4) + ks * 32);
        }
    }
    const int prow0 = tid >> 2;
    const int pc16 = (tid & 3) * 16;  // byte col
    const int pc8  = (tid & 3) * 8;   // element col
    unsigned soffs[2];
    soffs[0] = swz(prow0, pc16);
    soffs[1] = swz(prow0 + 64, pc16);
    const size_t wvbase = ((size_t)e * 2 * FFN + bx * 128 + prow0) * DMODEL + pc8;

    for (int mt = blockIdx.z; mt * 128 < cnt; mt += gridDim.z) {
        if (tid < 128) {
            int r = mt * 128 + tid;
            toks[tid] = (r < cnt) ? g_pair_tok[off + r] : -1;
        }
        __syncthreads();
        float acc[4][4][4];
#pragma unroll
        for (int m = 0; m < 4; ++m)
#pragma unroll
            for (int n = 0; n < 4; ++n)
#pragma unroll
                for (int q = 0; q < 4; ++q) acc[m][n][q] = 0.f;

        uint4 rAh[2][2], rBh[2][2];
        const uint4 z4 = make_uint4(0, 0, 0, 0);
#define G1_LDG(P)                                                                   \
        {                                                                           \
            _Pragma("unroll")                                                       \
            for (int q = 0; q < 2; ++q) {                                           \
                const int K0 = (P) * 64 + q * 32;                                   \
                _Pragma("unroll")                                                   \
                for (int j = 0; j < 2; ++j) {                                       \
                    const int row = prow0 + j * 64;                                 \
                    const int tok = toks[row];                                      \
                    if (tok >= 0) {                                                 \
                        size_t ao = (size_t)tok * DMODEL + K0 + pc8;                \
                        rAh[q][j] = *reinterpret_cast<const uint4*>(g_xs_hi + ao);  \
                    } else { rAh[q][j] = z4; }                                      \
                    rBh[q][j] = *reinterpret_cast<const uint4*>(                    \
                        g_wv1 + wvbase + j * (size_t)(64 * DMODEL) + K0);           \
                }                                                                   \
            }                                                                       \
        }
        G1_LDG(0)
        for (int p = 0; p < DMODEL / 64; ++p) {
            const unsigned sbase = (unsigned)(p & 1) * (2 * G1_STG);
#pragma unroll
            for (int q = 0; q < 2; ++q) {
                const unsigned so = sbase + q * G1_STG;
#pragma unroll
                for (int j = 0; j < 2; ++j) {
                    *reinterpret_cast<uint4*>(smem + so + G1_AH + soffs[j]) = rAh[q][j];
                    *reinterpret_cast<uint4*>(smem + so + G1_BH + soffs[j]) = rBh[q][j];
                }
            }
            if (p + 1 < DMODEL / 64) G1_LDG(p + 1)
            __syncthreads();
#pragma unroll
            for (int q = 0; q < 2; ++q) {
                const unsigned so = sbase + q * G1_STG;
#pragma unroll
                for (int ks = 0; ks < 2; ++ks) {
                    unsigned aH[4][4], bH[2][4];
#pragma unroll
                    for (int m = 0; m < 4; ++m)
                        ldm4(aH[m], sb + so + G1_AH + aoffs[ks][m]);
#pragma unroll
                    for (int np = 0; np < 2; ++np)
                        ldm4(bH[np], sb + so + G1_BH + boffs[ks][np]);
#pragma unroll
                    for (int np = 0; np < 2; ++np)
#pragma unroll
                        for (int hf = 0; hf < 2; ++hf)
#pragma unroll
                            for (int m = 0; m < 4; ++m)
                                mma16816(acc[m][np * 2 + hf], aH[m], &bH[np][hf * 2]);
                }
            }
            __syncthreads();
        }
        // ---- epilogue: thread-local SwiGLU, stage h tile in smem, coalesced store
        __half* hst = reinterpret_cast<__half*>(smem);
#pragma unroll
        for (int m = 0; m < 4; ++m)
#pragma unroll
            for (int hf = 0; hf < 2; ++hf) {
                const int row = wm * 64 + m * 16 + (lane >> 2) + hf * 8;
#pragma unroll
                for (int n = 0; n < 4; ++n) {
                    const int f = wn * 16 + n * 4 + (lane & 3);
                    const float gv = acc[m][n][hf * 2];
                    const float lv = acc[m][n][hf * 2 + 1];
                    const float hv = gv / (1.f + __expf(-gv)) * lv;
                    hst[row * HST_STRIDE + f] = __float2half_rn(hv);
                }
            }
        __syncthreads();
        {
            const int row = tid >> 1;
            const int c0 = (tid & 1) * 32;          // halves
            const int rl = mt * 128 + row;
            if (rl < cnt) {
                const uint4* s4 = reinterpret_cast<const uint4*>(hst + row * HST_STRIDE + c0);
                uint4* d4 = reinterpret_cast<uint4*>(
                    g_h_hi + (size_t)(off + rl) * FFN + bx * 64 + c0);
#pragma unroll
                for (int q = 0; q < 4; ++q) d4[q] = s4[q];
            }
        }
        __syncthreads();
    }
}

// ---------------- GEMM2 tile constants (A hi only + B hi) ----------------
#define G2_STG 16384
#define G2_AH 0
#define G2_BH 8192

// ---------------- GEMM2: out += gate * (h @ w2t^T), pair-chunk, 1-term ----------
__global__ void __launch_bounds__(256) gemm2_kernel(float* __restrict__ out) {
    extern __shared__ char smem[];
    const unsigned sb = smem_u32(smem);
    const int tid = threadIdx.x, lane = tid & 31, wid = tid >> 5;
    const int n0 = blockIdx.x * 128;
    const int e = blockIdx.y;
    const int off = g_off[e], cnt = g_off[e + 1] - off;

    const int wm = wid & 1, wn = wid >> 1;
    unsigned aoffs[2][4], boffs[2][2];
#pragma unroll
    for (int ks = 0; ks < 2; ++ks) {
#pragma unroll
        for (int m = 0; m < 4; ++m) {
            int r = wm * 64 + m * 16 + ((lane >> 3) & 1) * 8 + (lane & 7);
            aoffs[ks][m] = swz(r, ((lane >> 4) << 4) + ks * 32);
        }
#pragma unroll
        for (int np = 0; np < 2; ++np) {
            int r = wn * 32 + np * 16 + ((lane >> 4) << 3) + (lane & 7);
            boffs[ks][np] = swz(r, (((lane >> 3) & 1) << 4) + ks * 32);
        }
    }
    const int prow0 = tid >> 2;
    const int pc16 = (tid & 3) * 16;
    const int pc8  = (tid & 3) * 8;
    unsigned soffs[2];
    soffs[0] = swz(prow0, pc16);
    soffs[1] = swz(prow0 + 64, pc16);

    for (int mt = blockIdx.z; mt * 128 < cnt; mt += gridDim.z) {
        float acc[4][4][4];
#pragma unroll
        for (int m = 0; m < 4; ++m)
#pragma unroll
            for (int n = 0; n < 4; ++n)
#pragma unroll
                for (int q = 0; q < 4; ++q) acc[m][n][q] = 0.f;

        uint4 rAh[2][2], rBh[2][2];
        const uint4 z4 = make_uint4(0, 0, 0, 0);
#define G2_LDG(P)                                                                   \
        {                                                                           \
            _Pragma("unroll")                                                       \
            for (int q = 0; q < 2; ++q) {                                           \
                const int K0 = (P) * 64 + q * 32;                                   \
                _Pragma("unroll")                                                   \
                for (int j = 0; j < 2; ++j) {                                       \
                    const int row = prow0 + j * 64;                                 \
                    const int rl = mt * 128 + row;                                  \
                    if (rl < cnt) {                                                 \
                        size_t ao = (size_t)(off + rl) * FFN + K0 + pc8;            \
                        rAh[q][j] = *reinterpret_cast<const uint4*>(g_h_hi + ao);   \
                    } else { rAh[q][j] = z4; }                                      \
                    size_t bo = ((size_t)e * DMODEL + n0 + row) * FFN + K0 + pc8;   \
                    rBh[q][j] = *reinterpret_cast<const uint4*>(g_w2t_hi + bo);     \
                }                                                                   \
            }                                                                       \
        }
        G2_LDG(0)
        for (int p = 0; p < FFN / 64; ++p) {
            const unsigned sbase = (unsigned)(p & 1) * (2 * G2_STG);
#pragma unroll
            for (int q = 0; q < 2; ++q) {
                const unsigned so = sbase + q * G2_STG;
#pragma unroll
                for (int j = 0; j < 2; ++j) {
                    *reinterpret_cast<uint4*>(smem + so + G2_AH + soffs[j]) = rAh[q][j];
                    *reinterpret_cast<uint4*>(smem + so + G2_BH + soffs[j]) = rBh[q][j];
                }
            }
            if (p + 1 < FFN / 64) G2_LDG(p + 1)
            __syncthreads();
#pragma unroll
            for (int q = 0; q < 2; ++q) {
                const unsigned so = sbase + q * G2_STG;
#pragma unroll
                for (int ks = 0; ks < 2; ++ks) {
                    unsigned aH[4][4], bH[2][4];
#pragma unroll
                    for (int m = 0; m < 4; ++m)
                        ldm4(aH[m], sb + so + G2_AH + aoffs[ks][m]);
#pragma unroll
                    for (int np = 0; np < 2; ++np)
                        ldm4(bH[np], sb + so + G2_BH + boffs[ks][np]);
#pragma unroll
                    for (int np = 0; np < 2; ++np)
#pragma unroll
                        for (int hf = 0; hf < 2; ++hf)
#pragma unroll
                            for (int m = 0; m < 4; ++m)
                                mma16816(acc[m][np * 2 + hf], aH[m], &bH[np][hf * 2]);
                }
            }
            __syncthreads();
        }
        // epilogue: gate-scaled atomic combine (2 adds per output elem total)
#pragma unroll
        for (int m = 0; m < 4; ++m)
#pragma unroll
            for (int hf = 0; hf < 2; ++hf) {
                const int rl = mt * 128 + wm * 64 + m * 16 + (lane >> 2) + hf * 8;
                if (rl < cnt) {
                    const int   tok = g_pair_tok[off + rl];
                    const float gt  = g_pair_gate[off + rl];
                    float* dst = out + (size_t)tok * DMODEL + n0 + wn * 32 + (lane & 3) * 2;
#pragma unroll
                    for (int n = 0; n < 4; ++n) {
                        atomicAdd(dst + n * 8 + 0, gt * acc[m][n][hf * 2]);
                        atomicAdd(dst + n * 8 + 1, gt * acc[m][n][hf * 2 + 1]);
                    }
                }
            }
        __syncthreads();
    }
}

// ---------------- launch ----------------
extern "C" void kernel_launch(void* const* d_in, const int* in_sizes, int n_in,
                              void* d_out, int out_size) {
    const float* x  = (const float*)d_in[0];
    const float* w1 = (const float*)d_in[1];
    const float* v1 = (const float*)d_in[2];
    const float* w2 = (const float*)d_in[3];
    const float* rw = (const float*)d_in[4];
    float* out = (float*)d_out;

    cudaFuncSetAttribute(gemm1_kernel, cudaFuncAttributeMaxDynamicSharedMemorySize, 4 * G1_STG);
    cudaFuncSetAttribute(gemm2_kernel, cudaFuncAttributeMaxDynamicSharedMemorySize, 4 * G2_STG);

    const int nx4 = T_TOK * DMODEL / 4;
    const int nw4 = NEXP * FFN * DMODEL / 4;

    router_kernel<<<T_TOK, 256>>>(x, rw, out);                                // 1
    scatter_kernel<<<1, 256>>>();                                             // 2
    split_x_kernel<<<(nx4 + 255) / 256, 256>>>(x, nx4);                       // 3
    split_wv_kernel<<<dim3((nw4 + 255) / 256, 2), 256>>>(w1, v1, nw4);        // 4
    split_w2t_kernel<<<dim3(FFN / 32, DMODEL / 32, NEXP), dim3(32, 8)>>>(w2); // 5
    gemm1_kernel<<<dim3(32, NEXP, 4), 256, 4 * G1_STG>>>();                   // 6 <- profiled
    gemm2_kernel<<<dim3(DMODEL / 128, NEXP, 8), 256, 4 * G2_STG>>>(out);      // 7
}

// round 11
// speedup vs baseline: 2.2737x; 1.0826x over previous
#include <cuda_runtime.h>
#include <cuda_fp16.h>

#define T_TOK 4096
#define DMODEL 1024
#define NEXP 8
#define FFN 2048
#define TOPK 2
#define NPAIR (T_TOK * TOPK)

// ---------------- device scratch ----------------
__device__ int   g_cnt[NEXP];        // zero at module load; scatter re-zeros at end
__device__ int   g_off[NEXP + 1];
__device__ int   g_fill[NEXP];
__device__ int   g_pair_tok[NPAIR];
__device__ float g_pair_gate[NPAIR];
__device__ int   g_top_e[NPAIR];
__device__ float g_top_w[NPAIR];

__device__ __align__(16) __half g_xs_hi[(size_t)T_TOK * DMODEL];
// interleaved first-layer weights: row 2f = w1[f], row 2f+1 = v1[f]
__device__ __align__(16) __half g_wv1[(size_t)NEXP * 2 * FFN * DMODEL];
__device__ __align__(16) __half g_w2t_hi[(size_t)NEXP * DMODEL * FFN];
__device__ __align__(16) __half g_h_hi[(size_t)NPAIR * FFN];

// ---------------- helpers ----------------
__device__ __forceinline__ unsigned smem_u32(const void* p) {
    unsigned a;
    asm("{ .reg .u64 t; cvta.to.shared.u64 t, %1; cvt.u32.u64 %0, t; }"
        : "=r"(a) : "l"(p));
    return a;
}
// swizzled byte offset in a [rows][32 f16] tile (64B rows); c must be < 64
__device__ __forceinline__ unsigned swz(int row, int c) {
    return (unsigned)(row * 64 + (c ^ ((row & 6) << 3)));
}
__device__ __forceinline__ void ldm4(unsigned* r, unsigned addr) {
    asm volatile("ldmatrix.sync.aligned.m8n8.x4.shared.b16 {%0,%1,%2,%3}, [%4];"
                 : "=r"(r[0]), "=r"(r[1]), "=r"(r[2]), "=r"(r[3]) : "r"(addr));
}
__device__ __forceinline__ void mma16816(float* c, const unsigned* a, const unsigned* b) {
    asm volatile(
        "mma.sync.aligned.m16n8k16.row.col.f32.f16.f16.f32 "
        "{%0,%1,%2,%3}, {%4,%5,%6,%7}, {%8,%9}, {%0,%1,%2,%3};"
        : "+f"(c[0]), "+f"(c[1]), "+f"(c[2]), "+f"(c[3])
        : "r"(a[0]), "r"(a[1]), "r"(a[2]), "r"(a[3]), "r"(b[0]), "r"(b[1]));
}
__device__ __forceinline__ unsigned packh(__half a, __half b) {
    __half2 t = __halves2half2(a, b);
    return *reinterpret_cast<unsigned*>(&t);
}

// -------- router: logits -> top2 -> gates; also zeroes out and emits fp16 x ----
__global__ void router_kernel(const float* __restrict__ x, const float* __restrict__ rw,
                              float* __restrict__ out) {
    const int t   = blockIdx.x;
    const int tid = threadIdx.x;
    reinterpret_cast<float4*>(out + (size_t)t * DMODEL)[tid] = make_float4(0.f, 0.f, 0.f, 0.f);

    const float4 xr = reinterpret_cast<const float4*>(x + (size_t)t * DMODEL)[tid];
    // fused split_x: write fp16 copy of x
    {
        unsigned p0 = packh(__float2half_rn(xr.x), __float2half_rn(xr.y));
        unsigned p1 = packh(__float2half_rn(xr.z), __float2half_rn(xr.w));
        reinterpret_cast<uint2*>(g_xs_hi + (size_t)t * DMODEL)[tid] = make_uint2(p0, p1);
    }
    float part[NEXP];
#pragma unroll
    for (int e = 0; e < NEXP; ++e) {
        const float4 w = reinterpret_cast<const float4*>(rw + (size_t)e * DMODEL)[tid];
        part[e] = xr.x * w.x + xr.y * w.y + xr.z * w.z + xr.w * w.w;
    }
#pragma unroll
    for (int e = 0; e < NEXP; ++e)
#pragma unroll
        for (int o = 16; o > 0; o >>= 1)
            part[e] += __shfl_down_sync(0xffffffffu, part[e], o);
    __shared__ float sm[NEXP][8];
    const int warp = tid >> 5, lane = tid & 31;
    if (lane == 0)
#pragma unroll
        for (int e = 0; e < NEXP; ++e) sm[e][warp] = part[e];
    __syncthreads();
    if (tid == 0) {
        float lg[NEXP]; float mx = -1e30f;
#pragma unroll
        for (int e = 0; e < NEXP; ++e) {
            float s = 0.f;
#pragma unroll
            for (int w = 0; w < 8; ++w) s += sm[e][w];
            lg[e] = s; mx = fmaxf(mx, s);
        }
        float den = 0.f;
#pragma unroll
        for (int e = 0; e < NEXP; ++e) { lg[e] = expf(lg[e] - mx); den += lg[e]; }
#pragma unroll
        for (int e = 0; e < NEXP; ++e) lg[e] /= den;
        int e0 = 0; float v0 = lg[0];
#pragma unroll
        for (int e = 1; e < NEXP; ++e) if (lg[e] > v0) { v0 = lg[e]; e0 = e; }
        int e1 = -1; float v1 = -1.f;
#pragma unroll
        for (int e = 0; e < NEXP; ++e)
            if (e != e0 && lg[e] > v1) { v1 = lg[e]; e1 = e; }
        const float nrm = v0 + v1;
        g_top_e[t * 2 + 0] = e0; g_top_w[t * 2 + 0] = v0 / nrm;
        g_top_e[t * 2 + 1] = e1; g_top_w[t * 2 + 1] = v1 / nrm;
        atomicAdd(&g_cnt[e0], 1);
        atomicAdd(&g_cnt[e1], 1);
    }
}

// ---- scatter (single block): offsets + pair lists + counter reset for replay ----
__global__ void scatter_kernel() {
    if (threadIdx.x == 0) {
        int r = 0;
        g_off[0] = 0;
        for (int e = 0; e < NEXP; ++e) { r += g_cnt[e]; g_off[e + 1] = r; }
    }
    __syncthreads();
    for (int t = threadIdx.x; t < T_TOK; t += blockDim.x) {
#pragma unroll
        for (int k = 0; k < TOPK; ++k) {
            int e = g_top_e[t * TOPK + k];
            int pos = g_off[e] + atomicAdd(&g_fill[e], 1);
            g_pair_tok[pos]  = t;
            g_pair_gate[pos] = g_top_w[t * TOPK + k];
        }
    }
    __syncthreads();
    if (threadIdx.x < NEXP) { g_cnt[threadIdx.x] = 0; g_fill[threadIdx.x] = 0; }
}

// ------- w1+v1 convert fp32 -> fp16, interleaved rows (2f | 2f+1), one launch ----
__global__ void split_wv_kernel(const float* __restrict__ w1, const float* __restrict__ v1,
                                int n4) {
    int i = blockIdx.x * blockDim.x + threadIdx.x;
    if (i >= n4) return;
    const int sel = blockIdx.y;
    const float* s = sel ? v1 : w1;
    float4 v = reinterpret_cast<const float4*>(s)[i];
    unsigned p0 = packh(__float2half_rn(v.x), __float2half_rn(v.y));
    unsigned p1 = packh(__float2half_rn(v.z), __float2half_rn(v.w));
    const int row = i >> 8;               // i / (DMODEL/4)
    const int dc  = i & 255;              // float4 index within row
    const int e = row / FFN, f = row % FFN;
    const size_t drow = (size_t)e * 2 * FFN + 2 * f + sel;
    reinterpret_cast<uint2*>(g_wv1)[drow * 256 + dc] = make_uint2(p0, p1);
}

// ---------------- w2 transpose + fp16 convert: w2t[e][d][f] ----------------
__global__ void split_w2t_kernel(const float* __restrict__ w2) {
    __shared__ float t[32][33];
    const int e = blockIdx.z;
    const int f0 = blockIdx.x * 32, d0 = blockIdx.y * 32;
    const int tx = threadIdx.x, ty = threadIdx.y;   // 32 x 8
#pragma unroll
    for (int j = 0; j < 4; ++j)
        t[ty + j * 8][tx] = w2[((size_t)e * FFN + f0 + ty + j * 8) * DMODEL + d0 + tx];
    __syncthreads();
#pragma unroll
    for (int j = 0; j < 4; ++j) {
        const int dl = ty + j * 8;
        g_w2t_hi[((size_t)e * DMODEL + d0 + dl) * FFN + f0 + tx] =
            __float2half_rn(t[tx][dl]);
    }
}

// ---------------- GEMM1 tile constants ----------------
#define G1_STG 16384
#define G1_AH 0
#define G1_BH 8192
#define HST_STRIDE 72   // halves per row in epilogue staging (bank-shift padding)

// ---- GEMM1 (fused): h = silu(x@w1^T)*(x@v1^T) via interleaved B rows ----------
// Single-sync double-buffered mainloop (trailing sync removed; provably race-free).
__global__ void __launch_bounds__(256) gemm1_kernel() {
    extern __shared__ char smem[];
    __shared__ int toks[128];
    const unsigned sb = smem_u32(smem);
    const int tid = threadIdx.x, lane = tid & 31, wid = tid >> 5;
    const int bx = blockIdx.x;              // f-tile: [bx*64, bx*64+64)
    const int e = blockIdx.y;
    const int off = g_off[e], cnt = g_off[e + 1] - off;

    const int wm = wid & 1, wn = wid >> 1;
    unsigned aoffs[2][4], boffs[2][2];
#pragma unroll
    for (int ks = 0; ks < 2; ++ks) {
#pragma unroll
        for (int m = 0; m < 4; ++m) {
            int r = wm * 64 + m * 16 + ((lane >> 3) & 1) * 8 + (lane & 7);
            aoffs[ks][m] = swz(r, ((lane >> 4) << 4) + ks * 32);
        }
#pragma unroll
        for (int np = 0; np < 2; ++np) {
            int r = wn * 32 + np * 16 + ((lane >> 4) << 3) + (lane & 7);
            boffs[ks][np] = swz(r, (((lane >> 3) & 1) << 4) + ks * 32);
        }
    }
    const int prow0 = tid >> 2;
    const int pc16 = (tid & 3) * 16;  // byte col
    const int pc8  = (tid & 3) * 8;   // element col
    unsigned soffs[2];
    soffs[0] = swz(prow0, pc16);
    soffs[1] = swz(prow0 + 64, pc16);
    const size_t wvbase = ((size_t)e * 2 * FFN + bx * 128 + prow0) * DMODEL + pc8;

    for (int mt = blockIdx.z; mt * 128 < cnt; mt += gridDim.z) {
        if (tid < 128) {
            int r = mt * 128 + tid;
            toks[tid] = (r < cnt) ? g_pair_tok[off + r] : -1;
        }
        __syncthreads();
        float acc[4][4][4];
#pragma unroll
        for (int m = 0; m < 4; ++m)
#pragma unroll
            for (int n = 0; n < 4; ++n)
#pragma unroll
                for (int q = 0; q < 4; ++q) acc[m][n][q] = 0.f;

        uint4 rAh[2][2], rBh[2][2];
        const uint4 z4 = make_uint4(0, 0, 0, 0);
#define G1_LDG(P)                                                                   \
        {                                                                           \
            _Pragma("unroll")                                                       \
            for (int q = 0; q < 2; ++q) {                                           \
                const int K0 = (P) * 64 + q * 32;                                   \
                _Pragma("unroll")                                                   \
                for (int j = 0; j < 2; ++j) {                                       \
                    const int row = prow0 + j * 64;                                 \
                    const int tok = toks[row];                                      \
                    if (tok >= 0) {                                                 \
                        size_t ao = (size_t)tok * DMODEL + K0 + pc8;                \
                        rAh[q][j] = *reinterpret_cast<const uint4*>(g_xs_hi + ao);  \
                    } else { rAh[q][j] = z4; }                                      \
                    rBh[q][j] = *reinterpret_cast<const uint4*>(                    \
                        g_wv1 + wvbase + j * (size_t)(64 * DMODEL) + K0);           \
                }                                                                   \
            }                                                                       \
        }
        G1_LDG(0)
        for (int p = 0; p < DMODEL / 64; ++p) {
            const unsigned sbase = (unsigned)(p & 1) * (2 * G1_STG);
#pragma unroll
            for (int q = 0; q < 2; ++q) {
                const unsigned so = sbase + q * G1_STG;
#pragma unroll
                for (int j = 0; j < 2; ++j) {
                    *reinterpret_cast<uint4*>(smem + so + G1_AH + soffs[j]) = rAh[q][j];
                    *reinterpret_cast<uint4*>(smem + so + G1_BH + soffs[j]) = rBh[q][j];
                }
            }
            if (p + 1 < DMODEL / 64) G1_LDG(p + 1)
            __syncthreads();
#pragma unroll
            for (int q = 0; q < 2; ++q) {
                const unsigned so = sbase + q * G1_STG;
#pragma unroll
                for (int ks = 0; ks < 2; ++ks) {
                    unsigned aH[4][4], bH[2][4];
#pragma unroll
                    for (int m = 0; m < 4; ++m)
                        ldm4(aH[m], sb + so + G1_AH + aoffs[ks][m]);
#pragma unroll
                    for (int np = 0; np < 2; ++np)
                        ldm4(bH[np], sb + so + G1_BH + boffs[ks][np]);
#pragma unroll
                    for (int np = 0; np < 2; ++np)
#pragma unroll
                        for (int hf = 0; hf < 2; ++hf)
#pragma unroll
                            for (int m = 0; m < 4; ++m)
                                mma16816(acc[m][np * 2 + hf], aH[m], &bH[np][hf * 2]);
                }
            }
            // no trailing sync: next-iter stores target the other buffer, and
            // stores two iters ahead are ordered by the next leading sync.
        }
        __syncthreads();   // all warps done reading smem before hst reuse
        // ---- epilogue: thread-local SwiGLU, stage h tile in smem, coalesced store
        __half* hst = reinterpret_cast<__half*>(smem);
#pragma unroll
        for (int m = 0; m < 4; ++m)
#pragma unroll
            for (int hf = 0; hf < 2; ++hf) {
                const int row = wm * 64 + m * 16 + (lane >> 2) + hf * 8;
#pragma unroll
                for (int n = 0; n < 4; ++n) {
                    const int f = wn * 16 + n * 4 + (lane & 3);
                    const float gv = acc[m][n][hf * 2];
                    const float lv = acc[m][n][hf * 2 + 1];
                    const float hv = gv / (1.f + __expf(-gv)) * lv;
                    hst[row * HST_STRIDE + f] = __float2half_rn(hv);
                }
            }
        __syncthreads();
        {
            const int row = tid >> 1;
            const int c0 = (tid & 1) * 32;          // halves
            const int rl = mt * 128 + row;
            if (rl < cnt) {
                const uint4* s4 = reinterpret_cast<const uint4*>(hst + row * HST_STRIDE + c0);
                uint4* d4 = reinterpret_cast<uint4*>(
                    g_h_hi + (size_t)(off + rl) * FFN + bx * 64 + c0);
#pragma unroll
                for (int q = 0; q < 4; ++q) d4[q] = s4[q];
            }
        }
        __syncthreads();
    }
}

// ---------------- GEMM2 tile constants (A hi only + B hi) ----------------
#define G2_STG 16384
#define G2_AH 0
#define G2_BH 8192

// ---------------- GEMM2: out += gate * (h @ w2t^T), single-sync mainloop --------
__global__ void __launch_bounds__(256) gemm2_kernel(float* __restrict__ out) {
    extern __shared__ char smem[];
    const unsigned sb = smem_u32(smem);
    const int tid = threadIdx.x, lane = tid & 31, wid = tid >> 5;
    const int n0 = blockIdx.x * 128;
    const int e = blockIdx.y;
    const int off = g_off[e], cnt = g_off[e + 1] - off;

    const int wm = wid & 1, wn = wid >> 1;
    unsigned aoffs[2][4], boffs[2][2];
#pragma unroll
    for (int ks = 0; ks < 2; ++ks) {
#pragma unroll
        for (int m = 0; m < 4; ++m) {
            int r = wm * 64 + m * 16 + ((lane >> 3) & 1) * 8 + (lane & 7);
            aoffs[ks][m] = swz(r, ((lane >> 4) << 4) + ks * 32);
        }
#pragma unroll
        for (int np = 0; np < 2; ++np) {
            int r = wn * 32 + np * 16 + ((lane >> 4) << 3) + (lane & 7);
            boffs[ks][np] = swz(r, (((lane >> 3) & 1) << 4) + ks * 32);
        }
    }
    const int prow0 = tid >> 2;
    const int pc16 = (tid & 3) * 16;
    const int pc8  = (tid & 3) * 8;
    unsigned soffs[2];
    soffs[0] = swz(prow0, pc16);
    soffs[1] = swz(prow0 + 64, pc16);

    for (int mt = blockIdx.z; mt * 128 < cnt; mt += gridDim.z) {
        float acc[4][4][4];
#pragma unroll
        for (int m = 0; m < 4; ++m)
#pragma unroll
            for (int n = 0; n < 4; ++n)
#pragma unroll
                for (int q = 0; q < 4; ++q) acc[m][n][q] = 0.f;

        uint4 rAh[2][2], rBh[2][2];
        const uint4 z4 = make_uint4(0, 0, 0, 0);
#define G2_LDG(P)                                                                   \
        {                                                                           \
            _Pragma("unroll")                                                       \
            for (int q = 0; q < 2; ++q) {                                           \
                const int K0 = (P) * 64 + q * 32;                                   \
                _Pragma("unroll")                                                   \
                for (int j = 0; j < 2; ++j) {                                       \
                    const int row = prow0 + j * 64;                                 \
                    const int rl = mt * 128 + row;                                  \
                    if (rl < cnt) {                                                 \
                        size_t ao = (size_t)(off + rl) * FFN + K0 + pc8;            \
                        rAh[q][j] = *reinterpret_cast<const uint4*>(g_h_hi + ao);   \
                    } else { rAh[q][j] = z4; }                                      \
                    size_t bo = ((size_t)e * DMODEL + n0 + row) * FFN + K0 + pc8;   \
                    rBh[q][j] = *reinterpret_cast<const uint4*>(g_w2t_hi + bo);     \
                }                                                                   \
            }                                                                       \
        }
        G2_LDG(0)
        for (int p = 0; p < FFN / 64; ++p) {
            const unsigned sbase = (unsigned)(p & 1) * (2 * G2_STG);
#pragma unroll
            for (int q = 0; q < 2; ++q) {
                const unsigned so = sbase + q * G2_STG;
#pragma unroll
                for (int j = 0; j < 2; ++j) {
                    *reinterpret_cast<uint4*>(smem + so + G2_AH + soffs[j]) = rAh[q][j];
                    *reinterpret_cast<uint4*>(smem + so + G2_BH + soffs[j]) = rBh[q][j];
                }
            }
            if (p + 1 < FFN / 64) G2_LDG(p + 1)
            __syncthreads();
#pragma unroll
            for (int q = 0; q < 2; ++q) {
                const unsigned so = sbase + q * G2_STG;
#pragma unroll
                for (int ks = 0; ks < 2; ++ks) {
                    unsigned aH[4][4], bH[2][4];
#pragma unroll
                    for (int m = 0; m < 4; ++m)
                        ldm4(aH[m], sb + so + G2_AH + aoffs[ks][m]);
#pragma unroll
                    for (int np = 0; np < 2; ++np)
                        ldm4(bH[np], sb + so + G2_BH + boffs[ks][np]);
#pragma unroll
                    for (int np = 0; np < 2; ++np)
#pragma unroll
                        for (int hf = 0; hf < 2; ++hf)
#pragma unroll
                            for (int m = 0; m < 4; ++m)
                                mma16816(acc[m][np * 2 + hf], aH[m], &bH[np][hf * 2]);
                }
            }
            // no trailing sync (single-sync double buffer)
        }
        // epilogue: gate-scaled atomic combine (2 adds per output elem total)
#pragma unroll
        for (int m = 0; m < 4; ++m)
#pragma unroll
            for (int hf = 0; hf < 2; ++hf) {
                const int rl = mt * 128 + wm * 64 + m * 16 + (lane >> 2) + hf * 8;
                if (rl < cnt) {
                    const int   tok = g_pair_tok[off + rl];
                    const float gt  = g_pair_gate[off + rl];
                    float* dst = out + (size_t)tok * DMODEL + n0 + wn * 32 + (lane & 3) * 2;
#pragma unroll
                    for (int n = 0; n < 4; ++n) {
                        atomicAdd(dst + n * 8 + 0, gt * acc[m][n][hf * 2]);
                        atomicAdd(dst + n * 8 + 1, gt * acc[m][n][hf * 2 + 1]);
                    }
                }
            }
        __syncthreads();   // protect smem buffers before next mt's stores
    }
}

// ---------------- launch ----------------
extern "C" void kernel_launch(void* const* d_in, const int* in_sizes, int n_in,
                              void* d_out, int out_size) {
    const float* x  = (const float*)d_in[0];
    const float* w1 = (const float*)d_in[1];
    const float* v1 = (const float*)d_in[2];
    const float* w2 = (const float*)d_in[3];
    const float* rw = (const float*)d_in[4];
    float* out = (float*)d_out;

    cudaFuncSetAttribute(gemm1_kernel, cudaFuncAttributeMaxDynamicSharedMemorySize, 4 * G1_STG);
    cudaFuncSetAttribute(gemm2_kernel, cudaFuncAttributeMaxDynamicSharedMemorySize, 4 * G2_STG);

    const int nw4 = NEXP * FFN * DMODEL / 4;

    router_kernel<<<T_TOK, 256>>>(x, rw, out);                                // 1
    scatter_kernel<<<1, 256>>>();                                             // 2
    split_wv_kernel<<<dim3((nw4 + 255) / 256, 2), 256>>>(w1, v1, nw4);        // 3
    split_w2t_kernel<<<dim3(FFN / 32, DMODEL / 32, NEXP), dim3(32, 8)>>>(w2); // 4
    gemm1_kernel<<<dim3(32, NEXP, 4), 256, 4 * G1_STG>>>();                   // 5
    gemm2_kernel<<<dim3(DMODEL / 128, NEXP, 8), 256, 4 * G2_STG>>>(out);      // 6 <- profiled
}

// round 12
// speedup vs baseline: 2.2812x; 1.0033x over previous
#include <cuda_runtime.h>
#include <cuda_fp16.h>

#define T_TOK 4096
#define DMODEL 1024
#define NEXP 8
#define FFN 2048
#define TOPK 2
#define NPAIR (T_TOK * TOPK)

// ---------------- device scratch ----------------
__device__ int   g_cnt[NEXP];        // zero at module load; scatter re-zeros at end
__device__ int   g_off[NEXP + 1];
__device__ int   g_fill[NEXP];
__device__ int   g_pair_tok[NPAIR];
__device__ float g_pair_gate[NPAIR];
__device__ int   g_top_e[NPAIR];
__device__ float g_top_w[NPAIR];

__device__ __align__(16) __half g_xs_hi[(size_t)T_TOK * DMODEL];
// interleaved first-layer weights: row 2f = w1[f], row 2f+1 = v1[f]
__device__ __align__(16) __half g_wv1[(size_t)NEXP * 2 * FFN * DMODEL];
__device__ __align__(16) __half g_w2t_hi[(size_t)NEXP * DMODEL * FFN];
__device__ __align__(16) __half g_h_hi[(size_t)NPAIR * FFN];

// ---------------- helpers ----------------
__device__ __forceinline__ unsigned smem_u32(const void* p) {
    unsigned a;
    asm("{ .reg .u64 t; cvta.to.shared.u64 t, %1; cvt.u32.u64 %0, t; }"
        : "=r"(a) : "l"(p));
    return a;
}
// swizzled byte offset in a [rows][32 f16] tile (64B rows); c must be < 64
__device__ __forceinline__ unsigned swz(int row, int c) {
    return (unsigned)(row * 64 + (c ^ ((row & 6) << 3)));
}
__device__ __forceinline__ void ldm4(unsigned* r, unsigned addr) {
    asm volatile("ldmatrix.sync.aligned.m8n8.x4.shared.b16 {%0,%1,%2,%3}, [%4];"
                 : "=r"(r[0]), "=r"(r[1]), "=r"(r[2]), "=r"(r[3]) : "r"(addr));
}
__device__ __forceinline__ void mma16816(float* c, const unsigned* a, const unsigned* b) {
    asm volatile(
        "mma.sync.aligned.m16n8k16.row.col.f32.f16.f16.f32 "
        "{%0,%1,%2,%3}, {%4,%5,%6,%7}, {%8,%9}, {%0,%1,%2,%3};"
        : "+f"(c[0]), "+f"(c[1]), "+f"(c[2]), "+f"(c[3])
        : "r"(a[0]), "r"(a[1]), "r"(a[2]), "r"(a[3]), "r"(b[0]), "r"(b[1]));
}
__device__ __forceinline__ unsigned packh(__half a, __half b) {
    __half2 t = __halves2half2(a, b);
    return *reinterpret_cast<unsigned*>(&t);
}

// -------- router: logits -> top2 -> gates; also zeroes out and emits fp16 x ----
__global__ void router_kernel(const float* __restrict__ x, const float* __restrict__ rw,
                              float* __restrict__ out) {
    const int t   = blockIdx.x;
    const int tid = threadIdx.x;
    reinterpret_cast<float4*>(out + (size_t)t * DMODEL)[tid] = make_float4(0.f, 0.f, 0.f, 0.f);

    const float4 xr = reinterpret_cast<const float4*>(x + (size_t)t * DMODEL)[tid];
    // fused split_x: write fp16 copy of x
    {
        unsigned p0 = packh(__float2half_rn(xr.x), __float2half_rn(xr.y));
        unsigned p1 = packh(__float2half_rn(xr.z), __float2half_rn(xr.w));
        reinterpret_cast<uint2*>(g_xs_hi + (size_t)t * DMODEL)[tid] = make_uint2(p0, p1);
    }
    float part[NEXP];
#pragma unroll
    for (int e = 0; e < NEXP; ++e) {
        const float4 w = reinterpret_cast<const float4*>(rw + (size_t)e * DMODEL)[tid];
        part[e] = xr.x * w.x + xr.y * w.y + xr.z * w.z + xr.w * w.w;
    }
#pragma unroll
    for (int e = 0; e < NEXP; ++e)
#pragma unroll
        for (int o = 16; o > 0; o >>= 1)
            part[e] += __shfl_down_sync(0xffffffffu, part[e], o);
    __shared__ float sm[NEXP][8];
    const int warp = tid >> 5, lane = tid & 31;
    if (lane == 0)
#pragma unroll
        for (int e = 0; e < NEXP; ++e) sm[e][warp] = part[e];
    __syncthreads();
    if (tid == 0) {
        float lg[NEXP]; float mx = -1e30f;
#pragma unroll
        for (int e = 0; e < NEXP; ++e) {
            float s = 0.f;
#pragma unroll
            for (int w = 0; w < 8; ++w) s += sm[e][w];
            lg[e] = s; mx = fmaxf(mx, s);
        }
        float den = 0.f;
#pragma unroll
        for (int e = 0; e < NEXP; ++e) { lg[e] = expf(lg[e] - mx); den += lg[e]; }
#pragma unroll
        for (int e = 0; e < NEXP; ++e) lg[e] /= den;
        int e0 = 0; float v0 = lg[0];
#pragma unroll
        for (int e = 1; e < NEXP; ++e) if (lg[e] > v0) { v0 = lg[e]; e0 = e; }
        int e1 = -1; float v1 = -1.f;
#pragma unroll
        for (int e = 0; e < NEXP; ++e)
            if (e != e0 && lg[e] > v1) { v1 = lg[e]; e1 = e; }
        const float nrm = v0 + v1;
        g_top_e[t * 2 + 0] = e0; g_top_w[t * 2 + 0] = v0 / nrm;
        g_top_e[t * 2 + 1] = e1; g_top_w[t * 2 + 1] = v1 / nrm;
        atomicAdd(&g_cnt[e0], 1);
        atomicAdd(&g_cnt[e1], 1);
    }
}

// ---- scatter (single block): offsets + pair lists + counter reset for replay ----
__global__ void scatter_kernel() {
    if (threadIdx.x == 0) {
        int r = 0;
        g_off[0] = 0;
        for (int e = 0; e < NEXP; ++e) { r += g_cnt[e]; g_off[e + 1] = r; }
    }
    __syncthreads();
    for (int t = threadIdx.x; t < T_TOK; t += blockDim.x) {
#pragma unroll
        for (int k = 0; k < TOPK; ++k) {
            int e = g_top_e[t * TOPK + k];
            int pos = g_off[e] + atomicAdd(&g_fill[e], 1);
            g_pair_tok[pos]  = t;
            g_pair_gate[pos] = g_top_w[t * TOPK + k];
        }
    }
    __syncthreads();
    if (threadIdx.x < NEXP) { g_cnt[threadIdx.x] = 0; g_fill[threadIdx.x] = 0; }
}

// ------- w1+v1 convert fp32 -> fp16, interleaved rows (2f | 2f+1), one launch ----
__global__ void split_wv_kernel(const float* __restrict__ w1, const float* __restrict__ v1,
                                int n4) {
    int i = blockIdx.x * blockDim.x + threadIdx.x;
    if (i >= n4) return;
    const int sel = blockIdx.y;
    const float* s = sel ? v1 : w1;
    float4 v = reinterpret_cast<const float4*>(s)[i];
    unsigned p0 = packh(__float2half_rn(v.x), __float2half_rn(v.y));
    unsigned p1 = packh(__float2half_rn(v.z), __float2half_rn(v.w));
    const int row = i >> 8;               // i / (DMODEL/4)
    const int dc  = i & 255;              // float4 index within row
    const int e = row / FFN, f = row % FFN;
    const size_t drow = (size_t)e * 2 * FFN + 2 * f + sel;
    reinterpret_cast<uint2*>(g_wv1)[drow * 256 + dc] = make_uint2(p0, p1);
}

// ---------------- w2 transpose + fp16 convert: w2t[e][d][f] ----------------
__global__ void split_w2t_kernel(const float* __restrict__ w2) {
    __shared__ float t[32][33];
    const int e = blockIdx.z;
    const int f0 = blockIdx.x * 32, d0 = blockIdx.y * 32;
    const int tx = threadIdx.x, ty = threadIdx.y;   // 32 x 8
#pragma unroll
    for (int j = 0; j < 4; ++j)
        t[ty + j * 8][tx] = w2[((size_t)e * FFN + f0 + ty + j * 8) * DMODEL + d0 + tx];
    __syncthreads();
#pragma unroll
    for (int j = 0; j < 4; ++j) {
        const int dl = ty + j * 8;
        g_w2t_hi[((size_t)e * DMODEL + d0 + dl) * FFN + f0 + tx] =
            __float2half_rn(t[tx][dl]);
    }
}

// ---------------- GEMM1 tile constants ----------------
#define G1_STG 16384
#define G1_AH 0
#define G1_BH 8192
#define HST_STRIDE 72   // halves per row in epilogue staging (bank-shift padding)

// ---- GEMM1 (fused): h = silu(x@w1^T)*(x@v1^T) via interleaved B rows ----------
// Single-sync mainloop over 128-wide k-groups (4 chunks per sync; 8-stage ring).
__global__ void __launch_bounds__(256) gemm1_kernel() {
    extern __shared__ char smem[];
    __shared__ int toks[128];
    const unsigned sb = smem_u32(smem);
    const int tid = threadIdx.x, lane = tid & 31, wid = tid >> 5;
    const int bx = blockIdx.x;              // f-tile: [bx*64, bx*64+64)
    const int e = blockIdx.y;
    const int off = g_off[e], cnt = g_off[e + 1] - off;

    const int wm = wid & 1, wn = wid >> 1;
    unsigned aoffs[2][4], boffs[2][2];
#pragma unroll
    for (int ks = 0; ks < 2; ++ks) {
#pragma unroll
        for (int m = 0; m < 4; ++m) {
            int r = wm * 64 + m * 16 + ((lane >> 3) & 1) * 8 + (lane & 7);
            aoffs[ks][m] = swz(r, ((lane >> 4) << 4) + ks * 32);
        }
#pragma unroll
        for (int np = 0; np < 2; ++np) {
            int r = wn * 32 + np * 16 + ((lane >> 4) << 3) + (lane & 7);
            boffs[ks][np] = swz(r, (((lane >> 3) & 1) << 4) + ks * 32);
        }
    }
    const int prow0 = tid >> 2;
    const int pc16 = (tid & 3) * 16;  // byte col
    const int pc8  = (tid & 3) * 8;   // element col
    unsigned soffs[2];
    soffs[0] = swz(prow0, pc16);
    soffs[1] = swz(prow0 + 64, pc16);
    const size_t wvbase = ((size_t)e * 2 * FFN + bx * 128 + prow0) * DMODEL + pc8;

    for (int mt = blockIdx.z; mt * 128 < cnt; mt += gridDim.z) {
        if (tid < 128) {
            int r = mt * 128 + tid;
            toks[tid] = (r < cnt) ? g_pair_tok[off + r] : -1;
        }
        __syncthreads();
        float acc[4][4][4];
#pragma unroll
        for (int m = 0; m < 4; ++m)
#pragma unroll
            for (int n = 0; n < 4; ++n)
#pragma unroll
                for (int q = 0; q < 4; ++q) acc[m][n][q] = 0.f;

        uint4 rAh[4][2], rBh[4][2];
        const uint4 z4 = make_uint4(0, 0, 0, 0);
        // load one 128-k group (4 chunks of 32) into regs
#define G1_LDG(P)                                                                   \
        {                                                                           \
            _Pragma("unroll")                                                       \
            for (int q = 0; q < 4; ++q) {                                           \
                const int K0 = (P) * 128 + q * 32;                                  \
                _Pragma("unroll")                                                   \
                for (int j = 0; j < 2; ++j) {                                       \
                    const int row = prow0 + j * 64;                                 \
                    const int tok = toks[row];                                      \
                    if (tok >= 0) {                                                 \
                        size_t ao = (size_t)tok * DMODEL + K0 + pc8;                \
                        rAh[q][j] = *reinterpret_cast<const uint4*>(g_xs_hi + ao);  \
                    } else { rAh[q][j] = z4; }                                      \
                    rBh[q][j] = *reinterpret_cast<const uint4*>(                    \
                        g_wv1 + wvbase + j * (size_t)(64 * DMODEL) + K0);           \
                }                                                                   \
            }                                                                       \
        }
        G1_LDG(0)
        for (int p = 0; p < DMODEL / 128; ++p) {
            const unsigned sbase = (unsigned)(p & 1) * (4 * G1_STG);
#pragma unroll
            for (int q = 0; q < 4; ++q) {
                const unsigned so = sbase + q * G1_STG;
#pragma unroll
                for (int j = 0; j < 2; ++j) {
                    *reinterpret_cast<uint4*>(smem + so + G1_AH + soffs[j]) = rAh[q][j];
                    *reinterpret_cast<uint4*>(smem + so + G1_BH + soffs[j]) = rBh[q][j];
                }
            }
            if (p + 1 < DMODEL / 128) G1_LDG(p + 1)
            __syncthreads();
#pragma unroll
            for (int q = 0; q < 4; ++q) {
                const unsigned so = sbase + q * G1_STG;
#pragma unroll
                for (int ks = 0; ks < 2; ++ks) {
                    unsigned aH[4][4], bH[2][4];
#pragma unroll
                    for (int m = 0; m < 4; ++m)
                        ldm4(aH[m], sb + so + G1_AH + aoffs[ks][m]);
#pragma unroll
                    for (int np = 0; np < 2; ++np)
                        ldm4(bH[np], sb + so + G1_BH + boffs[ks][np]);
#pragma unroll
                    for (int np = 0; np < 2; ++np)
#pragma unroll
                        for (int hf = 0; hf < 2; ++hf)
#pragma unroll
                            for (int m = 0; m < 4; ++m)
                                mma16816(acc[m][np * 2 + hf], aH[m], &bH[np][hf * 2]);
                }
            }
            // no trailing sync: single-sync ring (next stores hit the other half)
        }
        __syncthreads();   // all warps done reading smem before hst reuse
        // ---- epilogue: thread-local SwiGLU, stage h tile in smem, coalesced store
        __half* hst = reinterpret_cast<__half*>(smem);
#pragma unroll
        for (int m = 0; m < 4; ++m)
#pragma unroll
            for (int hf = 0; hf < 2; ++hf) {
                const int row = wm * 64 + m * 16 + (lane >> 2) + hf * 8;
#pragma unroll
                for (int n = 0; n < 4; ++n) {
                    const int f = wn * 16 + n * 4 + (lane & 3);
                    const float gv = acc[m][n][hf * 2];
                    const float lv = acc[m][n][hf * 2 + 1];
                    const float hv = gv / (1.f + __expf(-gv)) * lv;
                    hst[row * HST_STRIDE + f] = __float2half_rn(hv);
                }
            }
        __syncthreads();
        {
            const int row = tid >> 1;
            const int c0 = (tid & 1) * 32;          // halves
            const int rl = mt * 128 + row;
            if (rl < cnt) {
                const uint4* s4 = reinterpret_cast<const uint4*>(hst + row * HST_STRIDE + c0);
                uint4* d4 = reinterpret_cast<uint4*>(
                    g_h_hi + (size_t)(off + rl) * FFN + bx * 64 + c0);
#pragma unroll
                for (int q = 0; q < 4; ++q) d4[q] = s4[q];
            }
        }
        __syncthreads();
    }
}

// ---------------- GEMM2 tile constants (A hi only + B hi) ----------------
#define G2_STG 16384
#define G2_AH 0
#define G2_BH 8192

// ----- GEMM2: out += gate * (h @ w2t^T), single-sync 128-k groups (8-stage) -----
__global__ void __launch_bounds__(256) gemm2_kernel(float* __restrict__ out) {
    extern __shared__ char smem[];
    const unsigned sb = smem_u32(smem);
    const int tid = threadIdx.x, lane = tid & 31, wid = tid >> 5;
    const int n0 = blockIdx.x * 128;
    const int e = blockIdx.y;
    const int off = g_off[e], cnt = g_off[e + 1] - off;

    const int wm = wid & 1, wn = wid >> 1;
    unsigned aoffs[2][4], boffs[2][2];
#pragma unroll
    for (int ks = 0; ks < 2; ++ks) {
#pragma unroll
        for (int m = 0; m < 4; ++m) {
            int r = wm * 64 + m * 16 + ((lane >> 3) & 1) * 8 + (lane & 7);
            aoffs[ks][m] = swz(r, ((lane >> 4) << 4) + ks * 32);
        }
#pragma unroll
        for (int np = 0; np < 2; ++np) {
            int r = wn * 32 + np * 16 + ((lane >> 4) << 3) + (lane & 7);
            boffs[ks][np] = swz(r, (((lane >> 3) & 1) << 4) + ks * 32);
        }
    }
    const int prow0 = tid >> 2;
    const int pc16 = (tid & 3) * 16;
    const int pc8  = (tid & 3) * 8;
    unsigned soffs[2];
    soffs[0] = swz(prow0, pc16);
    soffs[1] = swz(prow0 + 64, pc16);

    for (int mt = blockIdx.z; mt * 128 < cnt; mt += gridDim.z) {
        float acc[4][4][4];
#pragma unroll
        for (int m = 0; m < 4; ++m)
#pragma unroll
            for (int n = 0; n < 4; ++n)
#pragma unroll
                for (int q = 0; q < 4; ++q) acc[m][n][q] = 0.f;

        uint4 rAh[4][2], rBh[4][2];
        const uint4 z4 = make_uint4(0, 0, 0, 0);
#define G2_LDG(P)                                                                   \
        {                                                                           \
            _Pragma("unroll")                                                       \
            for (int q = 0; q < 4; ++q) {                                           \
                const int K0 = (P) * 128 + q * 32;                                  \
                _Pragma("unroll")                                                   \
                for (int j = 0; j < 2; ++j) {                                       \
                    const int row = prow0 + j * 64;                                 \
                    const int rl = mt * 128 + row;                                  \
                    if (rl < cnt) {                                                 \
                        size_t ao = (size_t)(off + rl) * FFN + K0 + pc8;            \
                        rAh[q][j] = *reinterpret_cast<const uint4*>(g_h_hi + ao);   \
                    } else { rAh[q][j] = z4; }                                      \
                    size_t bo = ((size_t)e * DMODEL + n0 + row) * FFN + K0 + pc8;   \
                    rBh[q][j] = *reinterpret_cast<const uint4*>(g_w2t_hi + bo);     \
                }                                                                   \
            }                                                                       \
        }
        G2_LDG(0)
        for (int p = 0; p < FFN / 128; ++p) {
            const unsigned sbase = (unsigned)(p & 1) * (4 * G2_STG);
#pragma unroll
            for (int q = 0; q < 4; ++q) {
                const unsigned so = sbase + q * G2_STG;
#pragma unroll
                for (int j = 0; j < 2; ++j) {
                    *reinterpret_cast<uint4*>(smem + so + G2_AH + soffs[j]) = rAh[q][j];
                    *reinterpret_cast<uint4*>(smem + so + G2_BH + soffs[j]) = rBh[q][j];
                }
            }
            if (p + 1 < FFN / 128) G2_LDG(p + 1)
            __syncthreads();
#pragma unroll
            for (int q = 0; q < 4; ++q) {
                const unsigned so = sbase + q * G2_STG;
#pragma unroll
                for (int ks = 0; ks < 2; ++ks) {
                    unsigned aH[4][4], bH[2][4];
#pragma unroll
                    for (int m = 0; m < 4; ++m)
                        ldm4(aH[m], sb + so + G2_AH + aoffs[ks][m]);
#pragma unroll
                    for (int np = 0; np < 2; ++np)
                        ldm4(bH[np], sb + so + G2_BH + boffs[ks][np]);
#pragma unroll
                    for (int np = 0; np < 2; ++np)
#pragma unroll
                        for (int hf = 0; hf < 2; ++hf)
#pragma unroll
                            for (int m = 0; m < 4; ++m)
                                mma16816(acc[m][np * 2 + hf], aH[m], &bH[np][hf * 2]);
                }
            }
            // no trailing sync (single-sync ring)
        }
        // epilogue: gate-scaled atomic combine (2 adds per output elem total)
#pragma unroll
        for (int m = 0; m < 4; ++m)
#pragma unroll
            for (int hf = 0; hf < 2; ++hf) {
                const int rl = mt * 128 + wm * 64 + m * 16 + (lane >> 2) + hf * 8;
                if (rl < cnt) {
                    const int   tok = g_pair_tok[off + rl];
                    const float gt  = g_pair_gate[off + rl];
                    float* dst = out + (size_t)tok * DMODEL + n0 + wn * 32 + (lane & 3) * 2;
#pragma unroll
                    for (int n = 0; n < 4; ++n) {
                        atomicAdd(dst + n * 8 + 0, gt * acc[m][n][hf * 2]);
                        atomicAdd(dst + n * 8 + 1, gt * acc[m][n][hf * 2 + 1]);
                    }
                }
            }
        __syncthreads();   // protect smem buffers before next mt's stores
    }
}

// ---------------- launch ----------------
extern "C" void kernel_launch(void* const* d_in, const int* in_sizes, int n_in,
                              void* d_out, int out_size) {
    const float* x  = (const float*)d_in[0];
    const float* w1 = (const float*)d_in[1];
    const float* v1 = (const float*)d_in[2];
    const float* w2 = (const float*)d_in[3];
    const float* rw = (const float*)d_in[4];
    float* out = (float*)d_out;

    cudaFuncSetAttribute(gemm1_kernel, cudaFuncAttributeMaxDynamicSharedMemorySize, 8 * G1_STG);
    cudaFuncSetAttribute(gemm2_kernel, cudaFuncAttributeMaxDynamicSharedMemorySize, 8 * G2_STG);

    const int nw4 = NEXP * FFN * DMODEL / 4;

    router_kernel<<<T_TOK, 256>>>(x, rw, out);                                // 1
    scatter_kernel<<<1, 256>>>();                                             // 2
    split_wv_kernel<<<dim3((nw4 + 255) / 256, 2), 256>>>(w1, v1, nw4);        // 3
    split_w2t_kernel<<<dim3(FFN / 32, DMODEL / 32, NEXP), dim3(32, 8)>>>(w2); // 4
    gemm1_kernel<<<dim3(32, NEXP, 4), 256, 8 * G1_STG>>>();                   // 5
    gemm2_kernel<<<dim3(DMODEL / 128, NEXP, 8), 256, 8 * G2_STG>>>(out);      // 6 <- profiled
}